// round 14
// baseline (speedup 1.0000x reference)
#include <cuda_runtime.h>
#include <math_constants.h>

// Problem constants
#define BB 4
#define NN 4096
#define FF 15
#define AA 24
#define AFN 14
#define HID 10
#define KSEL 204
#define SCALE 0.31622776601683794f   // 1/sqrt(10)
#define RPB 4                        // rows per attn block (2 per group)
#define FULL 0xffffffffu

typedef unsigned long long ull;

// ---------------- scratch (device globals; no allocation allowed) ----------------
__device__ float g_q[BB * NN * HID];          // [b][n][d]
__device__ float g_kT[BB * HID * NN];         // [b][d][n]  (transposed, fp32)
__device__ float g_v[BB * NN * HID];          // [b][n][d]
__device__ float g_logits[BB * NN * 2];       // [b][n][c]

// ---------------- helpers ----------------
__device__ __forceinline__ unsigned orderf(float f) {
    unsigned u = __float_as_uint(f);
    return (u & 0x80000000u) ? ~u : (u | 0x80000000u);
}
__device__ __forceinline__ float unorderf(unsigned u) {
    return (u & 0x80000000u) ? __uint_as_float(u ^ 0x80000000u)
                             : __uint_as_float(~u);
}

// warp-collective: pick radix bucket from a 2-copy 256-bin histogram (suffix order),
// append byte to pref. One designated lane writes results.
__device__ __forceinline__ void sel256(const unsigned* __restrict__ h0,
                                       unsigned prefIn, int kneedIn, int lane,
                                       unsigned* prefOut, int* kneedOut) {
    unsigned h8[8];
    int part = 0;
#pragma unroll
    for (int i = 0; i < 8; i++) {
        unsigned s = h0[lane * 8 + i] + h0[256 + lane * 8 + i];
        h8[i] = s; part += (int)s;
    }
    int suff = part;
#pragma unroll
    for (int d2 = 1; d2 < 32; d2 <<= 1) {
        int v = __shfl_down_sync(FULL, suff, d2);
        if (lane + d2 < 32) suff += v;
    }
    int c = suff - part;
    bool found = false; unsigned bsel = 0; int krem = 0;
#pragma unroll
    for (int i = 7; i >= 0; i--) {
        int Cn = c; c += (int)h8[i];
        if (!found && c >= kneedIn && Cn < kneedIn) {
            bsel = (unsigned)(lane * 8 + i); krem = kneedIn - Cn; found = true;
        }
    }
    unsigned fm = __ballot_sync(FULL, found);
    int src = __ffs(fm) - 1;
    if (lane == src) { *prefOut = (prefIn << 8) | bsel; *kneedOut = krem; }
}

// ---------------- Kernel 1: conv features (warp per seq) + QKV projection ----------------
__global__ __launch_bounds__(256) void conv_qkv_kernel(
    const float* __restrict__ x,
    const float* __restrict__ cw2, const float* __restrict__ cb2,
    const float* __restrict__ cw3, const float* __restrict__ cb3,
    const float* __restrict__ cw4, const float* __restrict__ cb4,
    const float* __restrict__ cw5, const float* __restrict__ cb5,
    const float* __restrict__ cw6, const float* __restrict__ cb6,
    const float* __restrict__ cw7, const float* __restrict__ cb7,
    const float* __restrict__ wq, const float* __restrict__ bq,
    const float* __restrict__ wk, const float* __restrict__ bk,
    const float* __restrict__ wv, const float* __restrict__ bv) {
    __shared__ __align__(16) float wsm[FF * 56];   // [i][packed 56]
    __shared__ float bsm[AFN];
    __shared__ float xsm[8][FF * 32];              // per-seq x rows padded to 32

    const int tid = threadIdx.x;
    const int lane = tid & 31;
    const int w = tid >> 5;
    const int seq = blockIdx.x * 8 + w;

    for (int e = tid; e < FF * 56; e += 256) {
        int i = e / 56, r = e % 56;
        int f, dt;
        if (r < 6)       { f = r >> 1;            dt = r & 1; }
        else if (r < 15) { f = 3 + (r - 6) / 3;   dt = (r - 6) % 3; }
        else if (r < 27) { f = 6 + (r - 15) / 4;  dt = (r - 15) & 3; }
        else if (r < 37) { f = 9 + (r - 27) / 5;  dt = (r - 27) % 5; }
        else if (r < 49) { f = 11 + (r - 37) / 6; dt = (r - 37) % 6; }
        else             { f = 13;                dt = r - 49; }
        const float* src; int H, fl;
        if (f < 3)       { src = cw2; H = 2; fl = f; }
        else if (f < 6)  { src = cw3; H = 3; fl = f - 3; }
        else if (f < 9)  { src = cw4; H = 4; fl = f - 6; }
        else if (f < 11) { src = cw5; H = 5; fl = f - 9; }
        else if (f < 13) { src = cw6; H = 6; fl = f - 11; }
        else             { src = cw7; H = 7; fl = 0; }
        wsm[i * 56 + r] = src[(fl * FF + i) * H + dt];
    }
    if (tid < AFN) {
        float bv_;
        if (tid < 3)       bv_ = cb2[tid];
        else if (tid < 6)  bv_ = cb3[tid - 3];
        else if (tid < 9)  bv_ = cb4[tid - 6];
        else if (tid < 11) bv_ = cb5[tid - 9];
        else if (tid < 13) bv_ = cb6[tid - 11];
        else               bv_ = cb7[0];
        bsm[tid] = bv_;
    }

    const float* xg = x + (size_t)seq * (FF * AA);
    for (int idx = lane; idx < FF * AA; idx += 32) {
        int i = idx / AA, c = idx % AA;
        xsm[w][i * 32 + c] = xg[idx];
    }
    for (int p = lane; p < FF * 8; p += 32) {
        int i = p / 8, c = 24 + (p & 7);
        xsm[w][i * 32 + c] = 0.f;
    }
    __syncthreads();

    const int Hs[14] = {2,2,2,3,3,3,4,4,4,5,5,6,6,7};
    const int FO[14] = {0,2,4,6,9,12,15,19,23,27,32,37,43,49};
    float y[AFN];
#pragma unroll
    for (int f = 0; f < AFN; f++) y[f] = 0.f;
    const int t = lane;
    if (t < AA) {
#pragma unroll
        for (int i = 0; i < FF; i++) {
            float xw[7];
#pragma unroll
            for (int dt = 0; dt < 7; dt++) xw[dt] = xsm[w][i * 32 + t + dt];
            float W[56];
            const float4* wp = (const float4*)(wsm + i * 56);
#pragma unroll
            for (int q4 = 0; q4 < 14; q4++) ((float4*)W)[q4] = wp[q4];
#pragma unroll
            for (int f = 0; f < AFN; f++)
#pragma unroll
                for (int dt = 0; dt < Hs[f]; dt++)
                    y[f] += xw[dt] * W[FO[f] + dt];
        }
    }
    float feat[AFN];
#pragma unroll
    for (int f = 0; f < AFN; f++) {
        const int T = AA - Hs[f] + 1;
        float v = (t < T) ? y[f] : -CUDART_INF_F;
#pragma unroll
        for (int off = 16; off > 0; off >>= 1)
            v = fmaxf(v, __shfl_xor_sync(FULL, v, off));
        feat[f] = fmaxf(v + bsm[f], 0.f);
    }

    if (lane < 30) {
        int which = lane / 10, oo = lane % 10;
        const float* W; const float* Bv;
        if (which == 0)      { W = wq; Bv = bq; }
        else if (which == 1) { W = wk; Bv = bk; }
        else                 { W = wv; Bv = bv; }
        float acc = Bv[oo];
#pragma unroll
        for (int i = 0; i < AFN; i++) acc += feat[i] * W[oo * AFN + i];
        int b = seq >> 12, n = seq & 4095;
        if (which == 0)      g_q[(b * NN + n) * HID + oo] = acc;
        else if (which == 1) g_kT[(b * HID + oo) * NN + n] = acc;
        else                 g_v[(b * NN + n) * HID + oo] = acc;
    }
}

// ---------------- Kernel 2: attention — fused pass-0, two independent groups ----------------
// dynamic smem (u32): keys[RPB*NN] = 16384 | overlay O[2048]:
//   during Phase A: O[r*512 + copy*256 + bin]  = per-row pass-0 hist (2 copies)
//   after pass-0 selects, group g owns O[g*1024, (g+1)*1024):
//     hist1 = O + g*1024 (2 copies x 256) ; cand = (ull*)(O + g*1024 + 512) [256]
#define KEYS_U32 (RPB * NN)
#define SMEM_BYTES ((KEYS_U32 + 2048) * 4)

#define GBAR() asm volatile("bar.sync %0, %1;" :: "r"(g + 1), "r"(128) : "memory")

__global__ __launch_bounds__(256, 3) void attn_kernel(
    const float* __restrict__ wattn, const float* __restrict__ battn,
    const float* __restrict__ wmil, const float* __restrict__ bmil,
    float* __restrict__ out) {
    extern __shared__ unsigned smem_u[];
    unsigned* keys = smem_u;
    unsigned* O    = smem_u + KEYS_U32;

    __shared__ float    sh_q2[RPB * HID];
    __shared__ unsigned sh_pref8[2][2];
    __shared__ int      sh_kneed8[2][2];
    __shared__ unsigned sh_pref[2];
    __shared__ int      sh_kneed[2];
    __shared__ unsigned sh_cnt[2];
    __shared__ float    sh_wred[2][4];
    __shared__ float    sh_gctx[2][4][HID];
    __shared__ float    sh_sctx[2][HID];
    __shared__ float    sh_smax[2];

    const int b = blockIdx.y;
    const int r0 = blockIdx.x * RPB;
    const int tid = threadIdx.x;
    const int lane = tid & 31;
    const int wid = tid >> 5;
    const int g = wid >> 2;          // group 0: warps 0-3, group 1: warps 4-7
    const int gtid = tid & 127;
    const int gwid = wid & 3;
    const int hc = wid & 1;          // histogram copy

    if (tid < RPB * HID) sh_q2[tid] = g_q[((size_t)b * NN + r0) * HID + tid];
#pragma unroll
    for (int i = 0; i < 8; i++) O[tid + (i << 8)] = 0u;   // zero overlay (pass-0 hists)
    __syncthreads();

    // ---- Phase A: scores -> keys in smem + FUSED pass-0 top-byte histograms ----
    const float* kt = g_kT + (size_t)b * HID * NN;
#pragma unroll
    for (int h = 0; h < 2; h++) {
        float acc[RPB][8];
#pragma unroll
        for (int r = 0; r < RPB; r++)
#pragma unroll
            for (int i = 0; i < 8; i++) acc[r][i] = 0.f;
#pragma unroll
        for (int d = 0; d < HID; d++) {
            float kv[8];
#pragma unroll
            for (int i = 0; i < 8; i++) kv[i] = kt[d * NN + tid + ((h * 8 + i) << 8)];
#pragma unroll
            for (int r = 0; r < RPB; r++) {
                float qv = sh_q2[r * HID + d];
#pragma unroll
                for (int i = 0; i < 8; i++) acc[r][i] = fmaf(qv, kv[i], acc[r][i]);
            }
        }
#pragma unroll
        for (int r = 0; r < RPB; r++) {
            unsigned* h0 = O + r * 512 + hc * 256;
#pragma unroll
            for (int i = 0; i < 8; i++) {
                unsigned u = orderf(acc[r][i]);
                keys[r * NN + tid + ((h * 8 + i) << 8)] = u;
                atomicAdd(&h0[u >> 24], 1u);
            }
        }
    }
    __syncthreads();

    // ---- pass-0 selects, one warp per row (parallel) ----
    if ((gwid & 1) == 0) {
        const int rr = gwid >> 1;          // gwid 0 -> row 0, gwid 2 -> row 1
        const int r = g * 2 + rr;
        sel256(O + r * 512, 0u, KSEL, lane, &sh_pref8[g][rr], &sh_kneed8[g][rr]);
    }
    GBAR();

    unsigned* hist1 = O + g * 1024;                 // 2 copies x 256
    unsigned* hw1   = hist1 + hc * 256;
    ull*      gc    = (ull*)(O + g * 1024 + 512);   // 256 candidates

    // ---- each group processes its 2 rows (named barriers only) ----
    for (int rr = 0; rr < 2; rr++) {
        const int r = g * 2 + rr;
        const int row = r0 + r;
        const unsigned* krow = keys + r * NN;
        const unsigned pref8v = sh_pref8[g][rr];

        // -- clear pass-1 hist + init counter --
        hist1[gtid] = 0u; hist1[gtid + 128] = 0u;
        hist1[gtid + 256] = 0u; hist1[gtid + 384] = 0u;
        if (gtid == 0) sh_cnt[g] = 0u;
        GBAR();

        // -- pass 1: byte 1 within selected top-byte bucket --
#pragma unroll
        for (int i = 0; i < 32; i++) {
            unsigned u = krow[gtid + (i << 7)];
            if ((u >> 24) == pref8v) atomicAdd(&hw1[(u >> 16) & 255u], 1u);
        }
        GBAR();
        if (gwid == 0)
            sel256(hist1, pref8v, sh_kneed8[g][rr], lane, &sh_pref[g], &sh_kneed[g]);
        // zero candidate buffer while select runs (gc disjoint from hist1)
        gc[gtid] = 0ull; gc[gtid + 128] = 0ull;
        GBAR();
        const unsigned pref16 = sh_pref[g];

        // -- single-scan compact (atomic position base; sort canonicalizes order) --
#pragma unroll
        for (int i = 0; i < 32; i++) {
            unsigned x2 = gtid + (i << 7);
            unsigned u = krow[x2];
            bool p = (u >> 16) >= pref16;
            unsigned mm = __ballot_sync(FULL, p);
            if (mm) {
                unsigned wbase = 0;
                int leader = __ffs(mm) - 1;
                if (lane == leader) wbase = atomicAdd(&sh_cnt[g], (unsigned)__popc(mm));
                wbase = __shfl_sync(FULL, wbase, leader);
                if (p) {
                    unsigned pos = wbase + (unsigned)__popc(mm & ((1u << lane) - 1u));
                    if (pos < 256u) gc[pos] = ((ull)u << 32) | (ull)(~x2);
                }
            }
        }
        GBAR();
        unsigned totc = sh_cnt[g];

        if (totc > 256u) {
            // rare fallback: refine to exact 32-bit threshold (passes 2,3), recompact
            for (int pp = 2; pp < 4; pp++) {
                const int shift = 24 - 8 * pp;
                hist1[gtid] = 0u; hist1[gtid + 128] = 0u;
                hist1[gtid + 256] = 0u; hist1[gtid + 384] = 0u;
                GBAR();
                const unsigned prefc = sh_pref[g];
#pragma unroll
                for (int i = 0; i < 32; i++) {
                    unsigned u = krow[gtid + (i << 7)];
                    if ((u >> (shift + 8)) == prefc)
                        atomicAdd(&hw1[(u >> shift) & 255u], 1u);
                }
                GBAR();
                if (gwid == 0)
                    sel256(hist1, sh_pref[g], sh_kneed[g], lane, &sh_pref[g], &sh_kneed[g]);
                GBAR();
            }
            const unsigned T = sh_pref[g];
            if (gtid == 0) sh_cnt[g] = 0u;
            gc[gtid] = 0ull; gc[gtid + 128] = 0ull;
            GBAR();
#pragma unroll
            for (int i = 0; i < 32; i++) {
                unsigned x2 = gtid + (i << 7);
                unsigned u = krow[x2];
                bool p = (u >= T);
                unsigned mm = __ballot_sync(FULL, p);
                if (mm) {
                    unsigned wbase = 0;
                    int leader = __ffs(mm) - 1;
                    if (lane == leader) wbase = atomicAdd(&sh_cnt[g], (unsigned)__popc(mm));
                    wbase = __shfl_sync(FULL, wbase, leader);
                    if (p) {
                        unsigned pos = wbase + (unsigned)__popc(mm & ((1u << lane) - 1u));
                        if (pos < 256u) gc[pos] = ((ull)u << 32) | (ull)(~x2);
                    }
                }
            }
            GBAR();
        }

        // -- bitonic sort 256 elems, 128 threads x 2 (elem i: owner i&127, half i>>7) --
        // descending; composite key (value desc, index asc) == exact lax.top_k order
        ull v0 = gc[gtid], v1 = gc[gtid + 128];
        for (int k2 = 2; k2 <= 256; k2 <<= 1) {
            for (int j = k2 >> 1; j > 0; j >>= 1) {
                if (j == 128) {
                    ull mx = (v0 > v1) ? v0 : v1;
                    ull mn = (v0 > v1) ? v1 : v0;
                    v0 = mx; v1 = mn;
                } else if (j >= 32) {
                    gc[gtid] = v0; gc[gtid + 128] = v1;
                    GBAR();
                    ull o0 = gc[gtid ^ j], o1 = gc[(gtid ^ j) + 128];
                    GBAR();
                    {
                        bool up = ((gtid & k2) == 0);
                        bool lower = ((gtid & j) == 0);
                        bool tkm = (up == lower);
                        ull mx = (v0 > o0) ? v0 : o0, mn = (v0 > o0) ? o0 : v0;
                        v0 = tkm ? mx : mn;
                    }
                    {
                        int i1 = gtid + 128;
                        bool up = ((i1 & k2) == 0);
                        bool lower = ((i1 & j) == 0);
                        bool tkm = (up == lower);
                        ull mx = (v1 > o1) ? v1 : o1, mn = (v1 > o1) ? o1 : v1;
                        v1 = tkm ? mx : mn;
                    }
                } else {
                    ull o0 = __shfl_xor_sync(FULL, v0, j);
                    ull o1 = __shfl_xor_sync(FULL, v1, j);
                    {
                        bool up = ((gtid & k2) == 0);
                        bool lower = ((gtid & j) == 0);
                        bool tkm = (up == lower);
                        ull mx = (v0 > o0) ? v0 : o0, mn = (v0 > o0) ? o0 : v0;
                        v0 = tkm ? mx : mn;
                    }
                    {
                        int i1 = gtid + 128;
                        bool up = ((i1 & k2) == 0);
                        bool lower = ((i1 & j) == 0);
                        bool tkm = (up == lower);
                        ull mx = (v1 > o1) ? v1 : o1, mn = (v1 > o1) ? o1 : v1;
                        v1 = tkm ? mx : mn;
                    }
                }
            }
        }
        // thread gtid holds ranks gtid (v0) and gtid+128 (v1)

        if (gtid == 0) sh_smax[g] = unorderf((unsigned)(v0 >> 32)) * SCALE;
        GBAR();
        const float smax = sh_smax[g];

        // -- softmax: rank gtid always < KSEL; rank gtid+128 < KSEL iff gtid < KSEL-128 --
        const bool act1 = gtid < (KSEL - 128);
        float e0 = __expf(unorderf((unsigned)(v0 >> 32)) * SCALE - smax);
        float e1 = act1 ? __expf(unorderf((unsigned)(v1 >> 32)) * SCALE - smax) : 0.f;
        float s = e0 + e1;
#pragma unroll
        for (int off = 16; off > 0; off >>= 1) s += __shfl_xor_sync(FULL, s, off);
        if (lane == 0) sh_wred[g][gwid] = s;
        GBAR();
        const float tot = sh_wred[g][0] + sh_wred[g][1] + sh_wred[g][2] + sh_wred[g][3];
        const float inv = 1.f / tot;

        // -- probs out + V gather + context --
        float* orow = out + 8 + ((size_t)(b * NN + row)) * KSEL;
        const float* vbase = g_v + (size_t)b * NN * HID;
        float p0 = e0 * inv;
        orow[gtid] = p0;
        unsigned gidx0 = ~(unsigned)(v0 & 0xffffffffull);
        float cd[HID];
        {
            const float2* vp = (const float2*)(vbase + (size_t)gidx0 * HID);
            float2 a0 = vp[0], a1 = vp[1], a2 = vp[2], a3 = vp[3], a4 = vp[4];
            cd[0] = p0 * a0.x; cd[1] = p0 * a0.y;
            cd[2] = p0 * a1.x; cd[3] = p0 * a1.y;
            cd[4] = p0 * a2.x; cd[5] = p0 * a2.y;
            cd[6] = p0 * a3.x; cd[7] = p0 * a3.y;
            cd[8] = p0 * a4.x; cd[9] = p0 * a4.y;
        }
        if (act1) {
            float p1 = e1 * inv;
            orow[gtid + 128] = p1;
            unsigned gidx1 = ~(unsigned)(v1 & 0xffffffffull);
            const float2* vp = (const float2*)(vbase + (size_t)gidx1 * HID);
            float2 a0 = vp[0], a1 = vp[1], a2 = vp[2], a3 = vp[3], a4 = vp[4];
            cd[0] += p1 * a0.x; cd[1] += p1 * a0.y;
            cd[2] += p1 * a1.x; cd[3] += p1 * a1.y;
            cd[4] += p1 * a2.x; cd[5] += p1 * a2.y;
            cd[6] += p1 * a3.x; cd[7] += p1 * a3.y;
            cd[8] += p1 * a4.x; cd[9] += p1 * a4.y;
        }
#pragma unroll
        for (int d = 0; d < HID; d++)
#pragma unroll
            for (int off = 16; off > 0; off >>= 1)
                cd[d] += __shfl_xor_sync(FULL, cd[d], off);
        if (lane == 0) {
#pragma unroll
            for (int d = 0; d < HID; d++) sh_gctx[g][gwid][d] = cd[d];
        }
        GBAR();
        if (gtid < HID) {
            sh_sctx[g][gtid] = sh_gctx[g][0][gtid] + sh_gctx[g][1][gtid] +
                               sh_gctx[g][2][gtid] + sh_gctx[g][3][gtid];
        }
        GBAR();
        if (gwid == 0) {
            float sa = 0.f;
            if (lane < AFN) {
                sa = battn[lane];
#pragma unroll
                for (int d = 0; d < HID; d++) sa += sh_sctx[g][d] * wattn[lane * HID + d];
            }
            float t0 = (lane < AFN) ? sa * wmil[lane] : 0.f;
            float t1 = (lane < AFN) ? sa * wmil[AFN + lane] : 0.f;
#pragma unroll
            for (int off = 16; off > 0; off >>= 1) {
                t0 += __shfl_xor_sync(FULL, t0, off);
                t1 += __shfl_xor_sync(FULL, t1, off);
            }
            if (lane == 0) {
                g_logits[(b * NN + row) * 2 + 0] = t0 + bmil[0];
                g_logits[(b * NN + row) * 2 + 1] = t1 + bmil[1];
            }
        }
        GBAR();
    }
}

// ---------------- Kernel 3: deterministic pooled reduction (8 blocks) ----------------
__global__ __launch_bounds__(256) void pool_kernel(float* __restrict__ out) {
    __shared__ float wr[8];
    const int b = blockIdx.x >> 1, c = blockIdx.x & 1;
    const int tid = threadIdx.x, lane = tid & 31, w = tid >> 5;
    float acc = 0.f;
#pragma unroll
    for (int it = 0; it < NN / 256; it++)
        acc += g_logits[((size_t)b * NN + it * 256 + tid) * 2 + c];
#pragma unroll
    for (int off = 16; off > 0; off >>= 1) acc += __shfl_xor_sync(FULL, acc, off);
    if (lane == 0) wr[w] = acc;
    __syncthreads();
    if (tid == 0) {
        float t = 0.f;
#pragma unroll
        for (int i = 0; i < 8; i++) t += wr[i];
        out[b * 2 + c] = t * (1.0f / (float)NN);
    }
}

// ---------------- launcher ----------------
extern "C" void kernel_launch(void* const* d_in, const int* in_sizes, int n_in,
                              void* d_out, int out_size) {
    const float* x   = (const float*)d_in[0];
    const float* cw2 = (const float*)d_in[1];  const float* cb2 = (const float*)d_in[2];
    const float* cw3 = (const float*)d_in[3];  const float* cb3 = (const float*)d_in[4];
    const float* cw4 = (const float*)d_in[5];  const float* cb4 = (const float*)d_in[6];
    const float* cw5 = (const float*)d_in[7];  const float* cb5 = (const float*)d_in[8];
    const float* cw6 = (const float*)d_in[9];  const float* cb6 = (const float*)d_in[10];
    const float* cw7 = (const float*)d_in[11]; const float* cb7 = (const float*)d_in[12];
    const float* wq  = (const float*)d_in[13]; const float* bq  = (const float*)d_in[14];
    const float* wk  = (const float*)d_in[15]; const float* bk  = (const float*)d_in[16];
    const float* wv  = (const float*)d_in[17]; const float* bv  = (const float*)d_in[18];
    const float* wat = (const float*)d_in[19]; const float* bat = (const float*)d_in[20];
    const float* wm  = (const float*)d_in[21]; const float* bm  = (const float*)d_in[22];
    float* out = (float*)d_out;

    cudaFuncSetAttribute(attn_kernel, cudaFuncAttributeMaxDynamicSharedMemorySize, SMEM_BYTES);

    conv_qkv_kernel<<<(BB * NN) / 8, 256>>>(x, cw2, cb2, cw3, cb3, cw4, cb4,
                                            cw5, cb5, cw6, cb6, cw7, cb7,
                                            wq, bq, wk, bk, wv, bv);
    attn_kernel<<<dim3(NN / RPB, BB), 256, SMEM_BYTES>>>(wat, bat, wm, bm, out);
    pool_kernel<<<8, 256>>>(out);
}

// round 15
// speedup vs baseline: 1.0344x; 1.0344x over previous
#include <cuda_runtime.h>
#include <math_constants.h>

// Problem constants
#define BB 4
#define NN 4096
#define FF 15
#define AA 24
#define AFN 14
#define HID 10
#define KSEL 204
#define SCALE 0.31622776601683794f   // 1/sqrt(10)
#define RPB 4                        // rows per attn block (2 per group)
#define FULL 0xffffffffu

typedef unsigned long long ull;

// ---------------- scratch (device globals; no allocation allowed) ----------------
__device__ float g_q[BB * NN * HID];          // [b][n][d]
__device__ float g_kT[BB * HID * NN];         // [b][d][n]  (transposed, fp32)
__device__ float g_v[BB * NN * HID];          // [b][n][d]
__device__ float g_logits[BB * NN * 2];       // [b][n][c]

// ---------------- helpers ----------------
__device__ __forceinline__ unsigned orderf(float f) {
    unsigned u = __float_as_uint(f);
    return (u & 0x80000000u) ? ~u : (u | 0x80000000u);
}
__device__ __forceinline__ float unorderf(unsigned u) {
    return (u & 0x80000000u) ? __uint_as_float(u ^ 0x80000000u)
                             : __uint_as_float(~u);
}

// warp-collective: pick radix bucket from a 2-copy 256-bin histogram (suffix order),
// append byte to pref. One designated lane writes results.
__device__ __forceinline__ void sel256(const unsigned* __restrict__ h0,
                                       unsigned prefIn, int kneedIn, int lane,
                                       unsigned* prefOut, int* kneedOut) {
    unsigned h8[8];
    int part = 0;
#pragma unroll
    for (int i = 0; i < 8; i++) {
        unsigned s = h0[lane * 8 + i] + h0[256 + lane * 8 + i];
        h8[i] = s; part += (int)s;
    }
    int suff = part;
#pragma unroll
    for (int d2 = 1; d2 < 32; d2 <<= 1) {
        int v = __shfl_down_sync(FULL, suff, d2);
        if (lane + d2 < 32) suff += v;
    }
    int c = suff - part;
    bool found = false; unsigned bsel = 0; int krem = 0;
#pragma unroll
    for (int i = 7; i >= 0; i--) {
        int Cn = c; c += (int)h8[i];
        if (!found && c >= kneedIn && Cn < kneedIn) {
            bsel = (unsigned)(lane * 8 + i); krem = kneedIn - Cn; found = true;
        }
    }
    unsigned fm = __ballot_sync(FULL, found);
    int src = __ffs(fm) - 1;
    if (lane == src) { *prefOut = (prefIn << 8) | bsel; *kneedOut = krem; }
}

// ---------------- Kernel 1: conv features (warp per seq) + QKV projection ----------------
__global__ __launch_bounds__(256) void conv_qkv_kernel(
    const float* __restrict__ x,
    const float* __restrict__ cw2, const float* __restrict__ cb2,
    const float* __restrict__ cw3, const float* __restrict__ cb3,
    const float* __restrict__ cw4, const float* __restrict__ cb4,
    const float* __restrict__ cw5, const float* __restrict__ cb5,
    const float* __restrict__ cw6, const float* __restrict__ cb6,
    const float* __restrict__ cw7, const float* __restrict__ cb7,
    const float* __restrict__ wq, const float* __restrict__ bq,
    const float* __restrict__ wk, const float* __restrict__ bk,
    const float* __restrict__ wv, const float* __restrict__ bv) {
    __shared__ __align__(16) float wsm[FF * 56];   // [i][packed 56]
    __shared__ float bsm[AFN];
    __shared__ float xsm[8][FF * 32];              // per-seq x rows padded to 32

    const int tid = threadIdx.x;
    const int lane = tid & 31;
    const int w = tid >> 5;
    const int seq = blockIdx.x * 8 + w;

    for (int e = tid; e < FF * 56; e += 256) {
        int i = e / 56, r = e % 56;
        int f, dt;
        if (r < 6)       { f = r >> 1;            dt = r & 1; }
        else if (r < 15) { f = 3 + (r - 6) / 3;   dt = (r - 6) % 3; }
        else if (r < 27) { f = 6 + (r - 15) / 4;  dt = (r - 15) & 3; }
        else if (r < 37) { f = 9 + (r - 27) / 5;  dt = (r - 27) % 5; }
        else if (r < 49) { f = 11 + (r - 37) / 6; dt = (r - 37) % 6; }
        else             { f = 13;                dt = r - 49; }
        const float* src; int H, fl;
        if (f < 3)       { src = cw2; H = 2; fl = f; }
        else if (f < 6)  { src = cw3; H = 3; fl = f - 3; }
        else if (f < 9)  { src = cw4; H = 4; fl = f - 6; }
        else if (f < 11) { src = cw5; H = 5; fl = f - 9; }
        else if (f < 13) { src = cw6; H = 6; fl = f - 11; }
        else             { src = cw7; H = 7; fl = 0; }
        wsm[i * 56 + r] = src[(fl * FF + i) * H + dt];
    }
    if (tid < AFN) {
        float bv_;
        if (tid < 3)       bv_ = cb2[tid];
        else if (tid < 6)  bv_ = cb3[tid - 3];
        else if (tid < 9)  bv_ = cb4[tid - 6];
        else if (tid < 11) bv_ = cb5[tid - 9];
        else if (tid < 13) bv_ = cb6[tid - 11];
        else               bv_ = cb7[0];
        bsm[tid] = bv_;
    }

    const float* xg = x + (size_t)seq * (FF * AA);
    for (int idx = lane; idx < FF * AA; idx += 32) {
        int i = idx / AA, c = idx % AA;
        xsm[w][i * 32 + c] = xg[idx];
    }
    for (int p = lane; p < FF * 8; p += 32) {
        int i = p / 8, c = 24 + (p & 7);
        xsm[w][i * 32 + c] = 0.f;
    }
    __syncthreads();

    const int Hs[14] = {2,2,2,3,3,3,4,4,4,5,5,6,6,7};
    const int FO[14] = {0,2,4,6,9,12,15,19,23,27,32,37,43,49};
    float y[AFN];
#pragma unroll
    for (int f = 0; f < AFN; f++) y[f] = 0.f;
    const int t = lane;
    if (t < AA) {
#pragma unroll
        for (int i = 0; i < FF; i++) {
            float xw[7];
#pragma unroll
            for (int dt = 0; dt < 7; dt++) xw[dt] = xsm[w][i * 32 + t + dt];
            float W[56];
            const float4* wp = (const float4*)(wsm + i * 56);
#pragma unroll
            for (int q4 = 0; q4 < 14; q4++) ((float4*)W)[q4] = wp[q4];
#pragma unroll
            for (int f = 0; f < AFN; f++)
#pragma unroll
                for (int dt = 0; dt < Hs[f]; dt++)
                    y[f] += xw[dt] * W[FO[f] + dt];
        }
    }
    float feat[AFN];
#pragma unroll
    for (int f = 0; f < AFN; f++) {
        const int T = AA - Hs[f] + 1;
        float v = (t < T) ? y[f] : -CUDART_INF_F;
#pragma unroll
        for (int off = 16; off > 0; off >>= 1)
            v = fmaxf(v, __shfl_xor_sync(FULL, v, off));
        feat[f] = fmaxf(v + bsm[f], 0.f);
    }

    if (lane < 30) {
        int which = lane / 10, oo = lane % 10;
        const float* W; const float* Bv;
        if (which == 0)      { W = wq; Bv = bq; }
        else if (which == 1) { W = wk; Bv = bk; }
        else                 { W = wv; Bv = bv; }
        float acc = Bv[oo];
#pragma unroll
        for (int i = 0; i < AFN; i++) acc += feat[i] * W[oo * AFN + i];
        int b = seq >> 12, n = seq & 4095;
        if (which == 0)      g_q[(b * NN + n) * HID + oo] = acc;
        else if (which == 1) g_kT[(b * HID + oo) * NN + n] = acc;
        else                 g_v[(b * NN + n) * HID + oo] = acc;
    }
}

// ---------------- Kernel 2: attention — two independent 128-thread groups ----------------
// dynamic smem (u32): keys[RPB*NN]=16384 | hist[4*256] | cand[2*256 ull]
// group g: hist1 = hist + g*512 (2 copies); gc = cand + g*256.
// pass-0 hist overlays gc (dead then); sort ping-pongs between gc and hist1 region.
#define KEYS_U32 (RPB * NN)
#define SMEM_BYTES (KEYS_U32 * 4 + 4 * 256 * 4 + 2 * 256 * 8)

#define GBAR() asm volatile("bar.sync %0, %1;" :: "r"(g + 1), "r"(128) : "memory")

__global__ __launch_bounds__(256, 3) void attn_kernel(
    const float* __restrict__ wattn, const float* __restrict__ battn,
    const float* __restrict__ wmil, const float* __restrict__ bmil,
    float* __restrict__ out) {
    extern __shared__ unsigned smem_u[];
    unsigned* keys = smem_u;
    unsigned* hist = smem_u + KEYS_U32;
    ull*      cand = (ull*)(smem_u + KEYS_U32 + 4 * 256);

    __shared__ float    sh_q2[RPB * HID];
    __shared__ unsigned sh_pref[2];
    __shared__ int      sh_kneed[2];
    __shared__ unsigned sh_cnt[2];
    __shared__ float    sh_wred[2][4];
    __shared__ float    sh_gctx[2][4][HID];
    __shared__ float    sh_sctx[2][HID];
    __shared__ float    sh_smax[2];

    const int b = blockIdx.y;
    const int r0 = blockIdx.x * RPB;
    const int tid = threadIdx.x;
    const int lane = tid & 31;
    const int wid = tid >> 5;
    const int g = wid >> 2;          // group 0: warps 0-3, group 1: warps 4-7
    const int gtid = tid & 127;
    const int gwid = wid & 3;
    const int hc = wid & 1;          // histogram copy

    unsigned* hist1 = hist + g * 512;          // pass-1 hist (2 copies x 256)
    ull*      gc    = cand + g * 256;          // candidates / sort buffer A
    unsigned* hist0 = (unsigned*)gc;           // pass-0 hist overlays gc
    ull*      gb    = (ull*)hist1;             // sort buffer B overlays hist1
    unsigned* hw0   = hist0 + hc * 256;
    unsigned* hw1   = hist1 + hc * 256;

    if (tid < RPB * HID) sh_q2[tid] = g_q[((size_t)b * NN + r0) * HID + tid];
    __syncthreads();

    // ---- Phase A: scores -> ordered keys in smem (two 8-column halves, low regs) ----
    const float* kt = g_kT + (size_t)b * HID * NN;
#pragma unroll
    for (int h = 0; h < 2; h++) {
        float acc[RPB][8];
#pragma unroll
        for (int r = 0; r < RPB; r++)
#pragma unroll
            for (int i = 0; i < 8; i++) acc[r][i] = 0.f;
#pragma unroll
        for (int d = 0; d < HID; d++) {
            float kv[8];
#pragma unroll
            for (int i = 0; i < 8; i++) kv[i] = kt[d * NN + tid + ((h * 8 + i) << 8)];
#pragma unroll
            for (int r = 0; r < RPB; r++) {
                float qv = sh_q2[r * HID + d];
#pragma unroll
                for (int i = 0; i < 8; i++) acc[r][i] = fmaf(qv, kv[i], acc[r][i]);
            }
        }
#pragma unroll
        for (int r = 0; r < RPB; r++)
#pragma unroll
            for (int i = 0; i < 8; i++)
                keys[r * NN + tid + ((h * 8 + i) << 8)] = orderf(acc[r][i]);
    }
    __syncthreads();

    // ---- each group processes its 2 rows independently (named barriers only) ----
    for (int rr = 0; rr < 2; rr++) {
        const int r = g * 2 + rr;
        const int row = r0 + r;
        const unsigned* krow = keys + r * NN;
        const ull* krow64 = (const ull*)krow;

        // -- clear both hist regions + init counter --
        hist0[gtid] = 0u; hist0[gtid + 128] = 0u;
        hist0[gtid + 256] = 0u; hist0[gtid + 384] = 0u;
        hist1[gtid] = 0u; hist1[gtid + 128] = 0u;
        hist1[gtid + 256] = 0u; hist1[gtid + 384] = 0u;
        if (gtid == 0) sh_cnt[g] = 0u;
        GBAR();

        // -- pass 0: top byte (vectorized 2-key loads) --
#pragma unroll
        for (int i = 0; i < 16; i++) {
            ull kk = krow64[gtid + (i << 7)];
            atomicAdd(&hw0[(unsigned)kk >> 24], 1u);
            atomicAdd(&hw0[(unsigned)(kk >> 32) >> 24], 1u);
        }
        GBAR();
        if (gwid == 0) sel256(hist0, 0u, KSEL, lane, &sh_pref[g], &sh_kneed[g]);
        GBAR();
        const unsigned pref8v = sh_pref[g];

        // hist0 (== gc) is dead now: zero candidate buffer, then pass 1
        gc[gtid] = 0ull; gc[gtid + 128] = 0ull;
#pragma unroll
        for (int i = 0; i < 16; i++) {
            ull kk = krow64[gtid + (i << 7)];
            unsigned lo = (unsigned)kk, hi = (unsigned)(kk >> 32);
            if ((lo >> 24) == pref8v) atomicAdd(&hw1[(lo >> 16) & 255u], 1u);
            if ((hi >> 24) == pref8v) atomicAdd(&hw1[(hi >> 16) & 255u], 1u);
        }
        GBAR();
        if (gwid == 0)
            sel256(hist1, pref8v, sh_kneed[g], lane, &sh_pref[g], &sh_kneed[g]);
        GBAR();
        const unsigned pref16 = sh_pref[g];

        // -- single-scan compact (atomic base; sort canonicalizes order) --
#pragma unroll
        for (int i = 0; i < 16; i++) {
            ull kk = krow64[gtid + (i << 7)];
            unsigned lo = (unsigned)kk, hi = (unsigned)(kk >> 32);
            unsigned xlo = 2u * (unsigned)(gtid + (i << 7));
#pragma unroll
            for (int hsel = 0; hsel < 2; hsel++) {
                unsigned u = hsel ? hi : lo;
                unsigned x2 = xlo + (unsigned)hsel;
                bool p = (u >> 16) >= pref16;
                unsigned mm = __ballot_sync(FULL, p);
                if (mm) {
                    unsigned wbase = 0;
                    int leader = __ffs(mm) - 1;
                    if (lane == leader) wbase = atomicAdd(&sh_cnt[g], (unsigned)__popc(mm));
                    wbase = __shfl_sync(FULL, wbase, leader);
                    if (p) {
                        unsigned pos = wbase + (unsigned)__popc(mm & ((1u << lane) - 1u));
                        if (pos < 256u) gc[pos] = ((ull)u << 32) | (ull)(~x2);
                    }
                }
            }
        }
        GBAR();
        unsigned totc = sh_cnt[g];

        if (totc > 256u) {
            // rare fallback: refine to exact 32-bit threshold (passes 2,3), recompact
            for (int pp = 2; pp < 4; pp++) {
                const int shift = 24 - 8 * pp;
                hist1[gtid] = 0u; hist1[gtid + 128] = 0u;
                hist1[gtid + 256] = 0u; hist1[gtid + 384] = 0u;
                GBAR();
                const unsigned prefc = sh_pref[g];
#pragma unroll
                for (int i = 0; i < 32; i++) {
                    unsigned u = krow[gtid + (i << 7)];
                    if ((u >> (shift + 8)) == prefc)
                        atomicAdd(&hw1[(u >> shift) & 255u], 1u);
                }
                GBAR();
                if (gwid == 0)
                    sel256(hist1, sh_pref[g], sh_kneed[g], lane, &sh_pref[g], &sh_kneed[g]);
                GBAR();
            }
            const unsigned T = sh_pref[g];
            if (gtid == 0) sh_cnt[g] = 0u;
            gc[gtid] = 0ull; gc[gtid + 128] = 0ull;
            GBAR();
#pragma unroll
            for (int i = 0; i < 32; i++) {
                unsigned x2 = gtid + (i << 7);
                unsigned u = krow[x2];
                bool p = (u >= T);
                unsigned mm = __ballot_sync(FULL, p);
                if (mm) {
                    unsigned wbase = 0;
                    int leader = __ffs(mm) - 1;
                    if (lane == leader) wbase = atomicAdd(&sh_cnt[g], (unsigned)__popc(mm));
                    wbase = __shfl_sync(FULL, wbase, leader);
                    if (p) {
                        unsigned pos = wbase + (unsigned)__popc(mm & ((1u << lane) - 1u));
                        if (pos < 256u) gc[pos] = ((ull)u << 32) | (ull)(~x2);
                    }
                }
            }
            GBAR();
        }

        // -- bitonic sort 256 elems, 128 threads x 2, ping-pong smem (1 bar/exchange) --
        // descending; composite key (value desc, index asc) == exact lax.top_k order
        ull v0 = gc[gtid], v1 = gc[gtid + 128];
        int pb = 0;
        for (int k2 = 2; k2 <= 256; k2 <<= 1) {
            for (int j = k2 >> 1; j > 0; j >>= 1) {
                if (j == 128) {
                    ull mx = (v0 > v1) ? v0 : v1;
                    ull mn = (v0 > v1) ? v1 : v0;
                    v0 = mx; v1 = mn;
                } else if (j >= 32) {
                    ull* B = pb ? gb : gc;
                    pb ^= 1;
                    B[gtid] = v0; B[gtid + 128] = v1;
                    GBAR();
                    ull o0 = B[gtid ^ j], o1 = B[(gtid ^ j) + 128];
                    {
                        bool up = ((gtid & k2) == 0);
                        bool lower = ((gtid & j) == 0);
                        bool tkm = (up == lower);
                        ull mx = (v0 > o0) ? v0 : o0, mn = (v0 > o0) ? o0 : v0;
                        v0 = tkm ? mx : mn;
                    }
                    {
                        int i1 = gtid + 128;
                        bool up = ((i1 & k2) == 0);
                        bool lower = ((i1 & j) == 0);
                        bool tkm = (up == lower);
                        ull mx = (v1 > o1) ? v1 : o1, mn = (v1 > o1) ? o1 : v1;
                        v1 = tkm ? mx : mn;
                    }
                } else {
                    ull o0 = __shfl_xor_sync(FULL, v0, j);
                    ull o1 = __shfl_xor_sync(FULL, v1, j);
                    {
                        bool up = ((gtid & k2) == 0);
                        bool lower = ((gtid & j) == 0);
                        bool tkm = (up == lower);
                        ull mx = (v0 > o0) ? v0 : o0, mn = (v0 > o0) ? o0 : v0;
                        v0 = tkm ? mx : mn;
                    }
                    {
                        int i1 = gtid + 128;
                        bool up = ((i1 & k2) == 0);
                        bool lower = ((i1 & j) == 0);
                        bool tkm = (up == lower);
                        ull mx = (v1 > o1) ? v1 : o1, mn = (v1 > o1) ? o1 : v1;
                        v1 = tkm ? mx : mn;
                    }
                }
            }
        }
        // thread gtid holds ranks gtid (v0) and gtid+128 (v1)

        if (gtid == 0) sh_smax[g] = unorderf((unsigned)(v0 >> 32)) * SCALE;
        GBAR();
        const float smax = sh_smax[g];

        // -- softmax: rank gtid always < KSEL; rank gtid+128 < KSEL iff gtid < KSEL-128 --
        const bool act1 = gtid < (KSEL - 128);
        float e0 = __expf(unorderf((unsigned)(v0 >> 32)) * SCALE - smax);
        float e1 = act1 ? __expf(unorderf((unsigned)(v1 >> 32)) * SCALE - smax) : 0.f;
        float s = e0 + e1;
#pragma unroll
        for (int off = 16; off > 0; off >>= 1) s += __shfl_xor_sync(FULL, s, off);
        if (lane == 0) sh_wred[g][gwid] = s;
        GBAR();
        const float tot = sh_wred[g][0] + sh_wred[g][1] + sh_wred[g][2] + sh_wred[g][3];
        const float inv = 1.f / tot;

        // -- probs out + V gather + context --
        float* orow = out + 8 + ((size_t)(b * NN + row)) * KSEL;
        const float* vbase = g_v + (size_t)b * NN * HID;
        float p0 = e0 * inv;
        orow[gtid] = p0;
        unsigned gidx0 = ~(unsigned)(v0 & 0xffffffffull);
        float cd[HID];
        {
            const float2* vp = (const float2*)(vbase + (size_t)gidx0 * HID);
            float2 a0 = vp[0], a1 = vp[1], a2 = vp[2], a3 = vp[3], a4 = vp[4];
            cd[0] = p0 * a0.x; cd[1] = p0 * a0.y;
            cd[2] = p0 * a1.x; cd[3] = p0 * a1.y;
            cd[4] = p0 * a2.x; cd[5] = p0 * a2.y;
            cd[6] = p0 * a3.x; cd[7] = p0 * a3.y;
            cd[8] = p0 * a4.x; cd[9] = p0 * a4.y;
        }
        if (act1) {
            float p1 = e1 * inv;
            orow[gtid + 128] = p1;
            unsigned gidx1 = ~(unsigned)(v1 & 0xffffffffull);
            const float2* vp = (const float2*)(vbase + (size_t)gidx1 * HID);
            float2 a0 = vp[0], a1 = vp[1], a2 = vp[2], a3 = vp[3], a4 = vp[4];
            cd[0] += p1 * a0.x; cd[1] += p1 * a0.y;
            cd[2] += p1 * a1.x; cd[3] += p1 * a1.y;
            cd[4] += p1 * a2.x; cd[5] += p1 * a2.y;
            cd[6] += p1 * a3.x; cd[7] += p1 * a3.y;
            cd[8] += p1 * a4.x; cd[9] += p1 * a4.y;
        }
#pragma unroll
        for (int d = 0; d < HID; d++)
#pragma unroll
            for (int off = 16; off > 0; off >>= 1)
                cd[d] += __shfl_xor_sync(FULL, cd[d], off);
        if (lane == 0) {
#pragma unroll
            for (int d = 0; d < HID; d++) sh_gctx[g][gwid][d] = cd[d];
        }
        GBAR();
        if (gtid < HID) {
            sh_sctx[g][gtid] = sh_gctx[g][0][gtid] + sh_gctx[g][1][gtid] +
                               sh_gctx[g][2][gtid] + sh_gctx[g][3][gtid];
        }
        GBAR();
        if (gwid == 0) {
            float sa = 0.f;
            if (lane < AFN) {
                sa = battn[lane];
#pragma unroll
                for (int d = 0; d < HID; d++) sa += sh_sctx[g][d] * wattn[lane * HID + d];
            }
            float t0 = (lane < AFN) ? sa * wmil[lane] : 0.f;
            float t1 = (lane < AFN) ? sa * wmil[AFN + lane] : 0.f;
#pragma unroll
            for (int off = 16; off > 0; off >>= 1) {
                t0 += __shfl_xor_sync(FULL, t0, off);
                t1 += __shfl_xor_sync(FULL, t1, off);
            }
            if (lane == 0) {
                g_logits[(b * NN + row) * 2 + 0] = t0 + bmil[0];
                g_logits[(b * NN + row) * 2 + 1] = t1 + bmil[1];
            }
        }
        GBAR();
    }
}

// ---------------- Kernel 3: deterministic pooled reduction (8 blocks) ----------------
__global__ __launch_bounds__(256) void pool_kernel(float* __restrict__ out) {
    __shared__ float wr[8];
    const int b = blockIdx.x >> 1, c = blockIdx.x & 1;
    const int tid = threadIdx.x, lane = tid & 31, w = tid >> 5;
    float acc = 0.f;
#pragma unroll
    for (int it = 0; it < NN / 256; it++)
        acc += g_logits[((size_t)b * NN + it * 256 + tid) * 2 + c];
#pragma unroll
    for (int off = 16; off > 0; off >>= 1) acc += __shfl_xor_sync(FULL, acc, off);
    if (lane == 0) wr[w] = acc;
    __syncthreads();
    if (tid == 0) {
        float t = 0.f;
#pragma unroll
        for (int i = 0; i < 8; i++) t += wr[i];
        out[b * 2 + c] = t * (1.0f / (float)NN);
    }
}

// ---------------- launcher ----------------
extern "C" void kernel_launch(void* const* d_in, const int* in_sizes, int n_in,
                              void* d_out, int out_size) {
    const float* x   = (const float*)d_in[0];
    const float* cw2 = (const float*)d_in[1];  const float* cb2 = (const float*)d_in[2];
    const float* cw3 = (const float*)d_in[3];  const float* cb3 = (const float*)d_in[4];
    const float* cw4 = (const float*)d_in[5];  const float* cb4 = (const float*)d_in[6];
    const float* cw5 = (const float*)d_in[7];  const float* cb5 = (const float*)d_in[8];
    const float* cw6 = (const float*)d_in[9];  const float* cb6 = (const float*)d_in[10];
    const float* cw7 = (const float*)d_in[11]; const float* cb7 = (const float*)d_in[12];
    const float* wq  = (const float*)d_in[13]; const float* bq  = (const float*)d_in[14];
    const float* wk  = (const float*)d_in[15]; const float* bk  = (const float*)d_in[16];
    const float* wv  = (const float*)d_in[17]; const float* bv  = (const float*)d_in[18];
    const float* wat = (const float*)d_in[19]; const float* bat = (const float*)d_in[20];
    const float* wm  = (const float*)d_in[21]; const float* bm  = (const float*)d_in[22];
    float* out = (float*)d_out;

    cudaFuncSetAttribute(attn_kernel, cudaFuncAttributeMaxDynamicSharedMemorySize, SMEM_BYTES);

    conv_qkv_kernel<<<(BB * NN) / 8, 256>>>(x, cw2, cb2, cw3, cb3, cw4, cb4,
                                            cw5, cb5, cw6, cb6, cw7, cb7,
                                            wq, bq, wk, bk, wv, bv);
    attn_kernel<<<dim3(NN / RPB, BB), 256, SMEM_BYTES>>>(wat, bat, wm, bm, out);
    pool_kernel<<<8, 256>>>(out);
}

// round 16
// speedup vs baseline: 1.2378x; 1.1967x over previous
#include <cuda_runtime.h>
#include <math_constants.h>

// Problem constants
#define BB 4
#define NN 4096
#define FF 15
#define AA 24
#define AFN 14
#define HID 10
#define KSEL 204
#define SCALE 0.31622776601683794f   // 1/sqrt(10)
#define RPB 2                        // rows per attn block (1 per group)
#define FULL 0xffffffffu

typedef unsigned long long ull;

// ---------------- scratch (device globals; no allocation allowed) ----------------
__device__ float g_q[BB * NN * HID];          // [b][n][d]
__device__ float g_kT[BB * HID * NN];         // [b][d][n]  (transposed, fp32)
__device__ float g_v[BB * NN * HID];          // [b][n][d]
__device__ float g_logits[BB * NN * 2];       // [b][n][c]

// ---------------- helpers ----------------
__device__ __forceinline__ unsigned orderf(float f) {
    unsigned u = __float_as_uint(f);
    return (u & 0x80000000u) ? ~u : (u | 0x80000000u);
}
__device__ __forceinline__ float unorderf(unsigned u) {
    return (u & 0x80000000u) ? __uint_as_float(u ^ 0x80000000u)
                             : __uint_as_float(~u);
}

// ---------------- Kernel 1: conv features (warp per seq) + QKV projection ----------------
__global__ __launch_bounds__(256) void conv_qkv_kernel(
    const float* __restrict__ x,
    const float* __restrict__ cw2, const float* __restrict__ cb2,
    const float* __restrict__ cw3, const float* __restrict__ cb3,
    const float* __restrict__ cw4, const float* __restrict__ cb4,
    const float* __restrict__ cw5, const float* __restrict__ cb5,
    const float* __restrict__ cw6, const float* __restrict__ cb6,
    const float* __restrict__ cw7, const float* __restrict__ cb7,
    const float* __restrict__ wq, const float* __restrict__ bq,
    const float* __restrict__ wk, const float* __restrict__ bk,
    const float* __restrict__ wv, const float* __restrict__ bv) {
    __shared__ __align__(16) float wsm[FF * 56];   // [i][packed 56]
    __shared__ float bsm[AFN];
    __shared__ float xsm[8][FF * 32];              // per-seq x rows padded to 32

    const int tid = threadIdx.x;
    const int lane = tid & 31;
    const int w = tid >> 5;
    const int seq = blockIdx.x * 8 + w;

    for (int e = tid; e < FF * 56; e += 256) {
        int i = e / 56, r = e % 56;
        int f, dt;
        if (r < 6)       { f = r >> 1;            dt = r & 1; }
        else if (r < 15) { f = 3 + (r - 6) / 3;   dt = (r - 6) % 3; }
        else if (r < 27) { f = 6 + (r - 15) / 4;  dt = (r - 15) & 3; }
        else if (r < 37) { f = 9 + (r - 27) / 5;  dt = (r - 27) % 5; }
        else if (r < 49) { f = 11 + (r - 37) / 6; dt = (r - 37) % 6; }
        else             { f = 13;                dt = r - 49; }
        const float* src; int H, fl;
        if (f < 3)       { src = cw2; H = 2; fl = f; }
        else if (f < 6)  { src = cw3; H = 3; fl = f - 3; }
        else if (f < 9)  { src = cw4; H = 4; fl = f - 6; }
        else if (f < 11) { src = cw5; H = 5; fl = f - 9; }
        else if (f < 13) { src = cw6; H = 6; fl = f - 11; }
        else             { src = cw7; H = 7; fl = 0; }
        wsm[i * 56 + r] = src[(fl * FF + i) * H + dt];
    }
    if (tid < AFN) {
        float bv_;
        if (tid < 3)       bv_ = cb2[tid];
        else if (tid < 6)  bv_ = cb3[tid - 3];
        else if (tid < 9)  bv_ = cb4[tid - 6];
        else if (tid < 11) bv_ = cb5[tid - 9];
        else if (tid < 13) bv_ = cb6[tid - 11];
        else               bv_ = cb7[0];
        bsm[tid] = bv_;
    }

    const float* xg = x + (size_t)seq * (FF * AA);
    for (int idx = lane; idx < FF * AA; idx += 32) {
        int i = idx / AA, c = idx % AA;
        xsm[w][i * 32 + c] = xg[idx];
    }
    for (int p = lane; p < FF * 8; p += 32) {
        int i = p / 8, c = 24 + (p & 7);
        xsm[w][i * 32 + c] = 0.f;
    }
    __syncthreads();

    const int Hs[14] = {2,2,2,3,3,3,4,4,4,5,5,6,6,7};
    const int FO[14] = {0,2,4,6,9,12,15,19,23,27,32,37,43,49};
    float y[AFN];
#pragma unroll
    for (int f = 0; f < AFN; f++) y[f] = 0.f;
    const int t = lane;
    if (t < AA) {
#pragma unroll
        for (int i = 0; i < FF; i++) {
            float xw[7];
#pragma unroll
            for (int dt = 0; dt < 7; dt++) xw[dt] = xsm[w][i * 32 + t + dt];
            float W[56];
            const float4* wp = (const float4*)(wsm + i * 56);
#pragma unroll
            for (int q4 = 0; q4 < 14; q4++) ((float4*)W)[q4] = wp[q4];
#pragma unroll
            for (int f = 0; f < AFN; f++)
#pragma unroll
                for (int dt = 0; dt < Hs[f]; dt++)
                    y[f] += xw[dt] * W[FO[f] + dt];
        }
    }
    float feat[AFN];
#pragma unroll
    for (int f = 0; f < AFN; f++) {
        const int T = AA - Hs[f] + 1;
        float v = (t < T) ? y[f] : -CUDART_INF_F;
#pragma unroll
        for (int off = 16; off > 0; off >>= 1)
            v = fmaxf(v, __shfl_xor_sync(FULL, v, off));
        feat[f] = fmaxf(v + bsm[f], 0.f);
    }

    if (lane < 30) {
        int which = lane / 10, oo = lane % 10;
        const float* W; const float* Bv;
        if (which == 0)      { W = wq; Bv = bq; }
        else if (which == 1) { W = wk; Bv = bk; }
        else                 { W = wv; Bv = bv; }
        float acc = Bv[oo];
#pragma unroll
        for (int i = 0; i < AFN; i++) acc += feat[i] * W[oo * AFN + i];
        int b = seq >> 12, n = seq & 4095;
        if (which == 0)      g_q[(b * NN + n) * HID + oo] = acc;
        else if (which == 1) g_kT[(b * HID + oo) * NN + n] = acc;
        else                 g_v[(b * NN + n) * HID + oo] = acc;
    }
}

// ---------------- Kernel 2: attention — two groups, ONE row each, 5 CTAs/SM ----------------
// dynamic smem (bytes): keys RPB*NN*4 = 32768 | hist 4*256*4 = 4096 | cand 2*256*8 = 4096
#define KEYS_U32 (RPB * NN)
#define SMEM_BYTES (KEYS_U32 * 4 + 4 * 256 * 4 + 2 * 256 * 8)

#define GBAR() asm volatile("bar.sync %0, %1;" :: "r"(g + 1), "r"(128) : "memory")

__global__ __launch_bounds__(256, 5) void attn_kernel(
    const float* __restrict__ wattn, const float* __restrict__ battn,
    const float* __restrict__ wmil, const float* __restrict__ bmil,
    float* __restrict__ out) {
    extern __shared__ unsigned smem_u[];
    unsigned* keys = smem_u;
    unsigned* hist = smem_u + KEYS_U32;
    ull*      cand = (ull*)(smem_u + KEYS_U32 + 4 * 256);

    __shared__ float    sh_q2[RPB * HID];
    __shared__ unsigned sh_pref[2];
    __shared__ int      sh_kneed[2];
    __shared__ unsigned sh_wcnt[2][4];
    __shared__ float    sh_wred[2][4];
    __shared__ float    sh_gctx[2][4][HID];
    __shared__ float    sh_sctx[2][HID];
    __shared__ float    sh_smax[2];

    const int b = blockIdx.y;
    const int r0 = blockIdx.x * RPB;
    const int tid = threadIdx.x;
    const int lane = tid & 31;
    const int wid = tid >> 5;
    const int g = wid >> 2;          // group 0: warps 0-3, group 1: warps 4-7
    const int gtid = tid & 127;
    const int gwid = wid & 3;
    const int hc = wid & 1;          // histogram copy
    unsigned* hw = hist + (g * 2 + hc) * 256;   // 2 hist copies per group
    ull* gc = cand + g * 256;

    if (tid < RPB * HID) sh_q2[tid] = g_q[((size_t)b * NN + r0) * HID + tid];
    __syncthreads();

    // ---- Phase A: scores for 2 rows -> ordered keys in smem ----
    const float* kt = g_kT + (size_t)b * HID * NN;
#pragma unroll
    for (int h = 0; h < 2; h++) {
        float acc[RPB][8];
#pragma unroll
        for (int r = 0; r < RPB; r++)
#pragma unroll
            for (int i = 0; i < 8; i++) acc[r][i] = 0.f;
#pragma unroll
        for (int d = 0; d < HID; d++) {
            float kv[8];
#pragma unroll
            for (int i = 0; i < 8; i++) kv[i] = kt[d * NN + tid + ((h * 8 + i) << 8)];
#pragma unroll
            for (int r = 0; r < RPB; r++) {
                float qv = sh_q2[r * HID + d];
#pragma unroll
                for (int i = 0; i < 8; i++) acc[r][i] = fmaf(qv, kv[i], acc[r][i]);
            }
        }
#pragma unroll
        for (int r = 0; r < RPB; r++)
#pragma unroll
            for (int i = 0; i < 8; i++)
                keys[r * NN + tid + ((h * 8 + i) << 8)] = orderf(acc[r][i]);
    }
    __syncthreads();

    // ---- group g owns row r0+g; fully independent (named barriers only) ----
    {
        const int row = r0 + g;
        const unsigned* krow = keys + g * NN;

        // -- pass 0: top byte histogram --
        hist[(g * 2) * 256 + gtid] = 0u; hist[(g * 2) * 256 + gtid + 128] = 0u;
        hist[(g * 2 + 1) * 256 + gtid] = 0u; hist[(g * 2 + 1) * 256 + gtid + 128] = 0u;
        if (gtid == 0) { sh_pref[g] = 0u; sh_kneed[g] = KSEL; }
        GBAR();
#pragma unroll
        for (int i = 0; i < 32; i++)
            atomicAdd(&hw[krow[gtid + (i << 7)] >> 24], 1u);
        GBAR();
        if (gwid == 0) {
            unsigned pref = sh_pref[g];
            int kneed = sh_kneed[g];
            unsigned h8[8];
            int part = 0;
#pragma unroll
            for (int i = 0; i < 8; i++) {
                unsigned s = hist[(g * 2) * 256 + lane * 8 + i] +
                             hist[(g * 2 + 1) * 256 + lane * 8 + i];
                h8[i] = s; part += (int)s;
            }
            int suff = part;
#pragma unroll
            for (int d2 = 1; d2 < 32; d2 <<= 1) {
                int v = __shfl_down_sync(FULL, suff, d2);
                if (lane + d2 < 32) suff += v;
            }
            int c = suff - part;
            bool found = false; unsigned bsel = 0; int krem = 0;
#pragma unroll
            for (int i = 7; i >= 0; i--) {
                int Cn = c; c += (int)h8[i];
                if (!found && c >= kneed && Cn < kneed) {
                    bsel = (unsigned)(lane * 8 + i); krem = kneed - Cn; found = true;
                }
            }
            unsigned fm = __ballot_sync(FULL, found);
            int src = __ffs(fm) - 1;
            if (lane == src) { sh_pref[g] = (pref << 8) | bsel; sh_kneed[g] = krem; }
        }
        GBAR();
        const unsigned pref8 = sh_pref[g];

        // -- clear + pass 1: byte 1 within selected bucket --
        hist[(g * 2) * 256 + gtid] = 0u; hist[(g * 2) * 256 + gtid + 128] = 0u;
        hist[(g * 2 + 1) * 256 + gtid] = 0u; hist[(g * 2 + 1) * 256 + gtid + 128] = 0u;
        GBAR();
#pragma unroll
        for (int i = 0; i < 32; i++) {
            unsigned u = krow[gtid + (i << 7)];
            if ((u >> 24) == pref8) atomicAdd(&hw[(u >> 16) & 255u], 1u);
        }
        GBAR();
        if (gwid == 0) {
            unsigned pref = sh_pref[g];
            int kneed = sh_kneed[g];
            unsigned h8[8];
            int part = 0;
#pragma unroll
            for (int i = 0; i < 8; i++) {
                unsigned s = hist[(g * 2) * 256 + lane * 8 + i] +
                             hist[(g * 2 + 1) * 256 + lane * 8 + i];
                h8[i] = s; part += (int)s;
            }
            int suff = part;
#pragma unroll
            for (int d2 = 1; d2 < 32; d2 <<= 1) {
                int v = __shfl_down_sync(FULL, suff, d2);
                if (lane + d2 < 32) suff += v;
            }
            int c = suff - part;
            bool found = false; unsigned bsel = 0; int krem = 0;
#pragma unroll
            for (int i = 7; i >= 0; i--) {
                int Cn = c; c += (int)h8[i];
                if (!found && c >= kneed && Cn < kneed) {
                    bsel = (unsigned)(lane * 8 + i); krem = kneed - Cn; found = true;
                }
            }
            unsigned fm = __ballot_sync(FULL, found);
            int src = __ffs(fm) - 1;
            if (lane == src) { sh_pref[g] = (pref << 8) | bsel; sh_kneed[g] = krem; }
        }
        GBAR();
        const unsigned pref16 = sh_pref[g];

        // -- compact candidates (u>>16 >= pref16) into gc[256], atomic-free two-phase --
        unsigned totc;
        {
            unsigned wcnt = 0;
#pragma unroll
            for (int i = 0; i < 32; i++) {
                bool p = (krow[gtid + (i << 7)] >> 16) >= pref16;
                wcnt += (unsigned)__popc(__ballot_sync(FULL, p));
            }
            if (lane == 0) sh_wcnt[g][gwid] = wcnt;
            gc[gtid] = 0ull; gc[gtid + 128] = 0ull;
            GBAR();
            unsigned base = 0; totc = 0;
#pragma unroll
            for (int w2 = 0; w2 < 4; w2++) {
                unsigned c = sh_wcnt[g][w2];
                if (w2 < gwid) base += c;
                totc += c;
            }
#pragma unroll
            for (int i = 0; i < 32; i++) {
                unsigned x2 = gtid + (i << 7);
                unsigned u = krow[x2];
                bool p = (u >> 16) >= pref16;
                unsigned mm = __ballot_sync(FULL, p);
                if (p) {
                    unsigned pos = base + (unsigned)__popc(mm & ((1u << lane) - 1u));
                    if (pos < 256u) gc[pos] = ((ull)u << 32) | (ull)(~x2);
                }
                base += (unsigned)__popc(mm);
            }
            GBAR();
        }

        if (totc > 256u) {
            // rare fallback: refine to exact 32-bit threshold (passes 2,3), recompact
            for (int pp = 2; pp < 4; pp++) {
                const int shift = 24 - 8 * pp;
                hist[(g * 2) * 256 + gtid] = 0u; hist[(g * 2) * 256 + gtid + 128] = 0u;
                hist[(g * 2 + 1) * 256 + gtid] = 0u; hist[(g * 2 + 1) * 256 + gtid + 128] = 0u;
                GBAR();
                const unsigned prefc = sh_pref[g];
#pragma unroll
                for (int i = 0; i < 32; i++) {
                    unsigned u = krow[gtid + (i << 7)];
                    if ((u >> (shift + 8)) == prefc)
                        atomicAdd(&hw[(u >> shift) & 255u], 1u);
                }
                GBAR();
                if (gwid == 0) {
                    unsigned pref = sh_pref[g];
                    int kneed = sh_kneed[g];
                    unsigned h8[8];
                    int part = 0;
#pragma unroll
                    for (int i = 0; i < 8; i++) {
                        unsigned s = hist[(g * 2) * 256 + lane * 8 + i] +
                                     hist[(g * 2 + 1) * 256 + lane * 8 + i];
                        h8[i] = s; part += (int)s;
                    }
                    int suff = part;
#pragma unroll
                    for (int d2 = 1; d2 < 32; d2 <<= 1) {
                        int v = __shfl_down_sync(FULL, suff, d2);
                        if (lane + d2 < 32) suff += v;
                    }
                    int c = suff - part;
                    bool found = false; unsigned bsel = 0; int krem = 0;
#pragma unroll
                    for (int i = 7; i >= 0; i--) {
                        int Cn = c; c += (int)h8[i];
                        if (!found && c >= kneed && Cn < kneed) {
                            bsel = (unsigned)(lane * 8 + i); krem = kneed - Cn; found = true;
                        }
                    }
                    unsigned fm = __ballot_sync(FULL, found);
                    int src = __ffs(fm) - 1;
                    if (lane == src) { sh_pref[g] = (pref << 8) | bsel; sh_kneed[g] = krem; }
                }
                GBAR();
            }
            const unsigned T = sh_pref[g];
            unsigned wcnt = 0;
#pragma unroll
            for (int i = 0; i < 32; i++) {
                bool p = krow[gtid + (i << 7)] >= T;
                wcnt += (unsigned)__popc(__ballot_sync(FULL, p));
            }
            if (lane == 0) sh_wcnt[g][gwid] = wcnt;
            gc[gtid] = 0ull; gc[gtid + 128] = 0ull;
            GBAR();
            unsigned base = 0;
#pragma unroll
            for (int w2 = 0; w2 < 4; w2++)
                if (w2 < gwid) base += sh_wcnt[g][w2];
#pragma unroll
            for (int i = 0; i < 32; i++) {
                unsigned x2 = gtid + (i << 7);
                unsigned u = krow[x2];
                bool p = (u >= T);
                unsigned mm = __ballot_sync(FULL, p);
                if (p) {
                    unsigned pos = base + (unsigned)__popc(mm & ((1u << lane) - 1u));
                    if (pos < 256u) gc[pos] = ((ull)u << 32) | (ull)(~x2);
                }
                base += (unsigned)__popc(mm);
            }
            GBAR();
        }

        // -- bitonic sort 256 elems, 128 threads x 2 (elem i: owner i&127, half i>>7) --
        // descending; composite key (value desc, index asc) == exact lax.top_k order
        ull v0 = gc[gtid], v1 = gc[gtid + 128];
        for (int k2 = 2; k2 <= 256; k2 <<= 1) {
            for (int j = k2 >> 1; j > 0; j >>= 1) {
                if (j == 128) {
                    ull mx = (v0 > v1) ? v0 : v1;
                    ull mn = (v0 > v1) ? v1 : v0;
                    v0 = mx; v1 = mn;
                } else if (j >= 32) {
                    gc[gtid] = v0; gc[gtid + 128] = v1;
                    GBAR();
                    ull o0 = gc[gtid ^ j], o1 = gc[(gtid ^ j) + 128];
                    GBAR();
                    {
                        bool up = ((gtid & k2) == 0);
                        bool lower = ((gtid & j) == 0);
                        bool tkm = (up == lower);
                        ull mx = (v0 > o0) ? v0 : o0, mn = (v0 > o0) ? o0 : v0;
                        v0 = tkm ? mx : mn;
                    }
                    {
                        int i1 = gtid + 128;
                        bool up = ((i1 & k2) == 0);
                        bool lower = ((i1 & j) == 0);
                        bool tkm = (up == lower);
                        ull mx = (v1 > o1) ? v1 : o1, mn = (v1 > o1) ? o1 : v1;
                        v1 = tkm ? mx : mn;
                    }
                } else {
                    ull o0 = __shfl_xor_sync(FULL, v0, j);
                    ull o1 = __shfl_xor_sync(FULL, v1, j);
                    {
                        bool up = ((gtid & k2) == 0);
                        bool lower = ((gtid & j) == 0);
                        bool tkm = (up == lower);
                        ull mx = (v0 > o0) ? v0 : o0, mn = (v0 > o0) ? o0 : v0;
                        v0 = tkm ? mx : mn;
                    }
                    {
                        int i1 = gtid + 128;
                        bool up = ((i1 & k2) == 0);
                        bool lower = ((i1 & j) == 0);
                        bool tkm = (up == lower);
                        ull mx = (v1 > o1) ? v1 : o1, mn = (v1 > o1) ? o1 : v1;
                        v1 = tkm ? mx : mn;
                    }
                }
            }
        }
        // thread gtid holds ranks gtid (v0) and gtid+128 (v1)

        if (gtid == 0) sh_smax[g] = unorderf((unsigned)(v0 >> 32)) * SCALE;
        GBAR();
        const float smax = sh_smax[g];

        // -- softmax: rank gtid always < KSEL; rank gtid+128 < KSEL iff gtid < KSEL-128 --
        const bool act1 = gtid < (KSEL - 128);
        float e0 = __expf(unorderf((unsigned)(v0 >> 32)) * SCALE - smax);
        float e1 = act1 ? __expf(unorderf((unsigned)(v1 >> 32)) * SCALE - smax) : 0.f;
        float s = e0 + e1;
#pragma unroll
        for (int off = 16; off > 0; off >>= 1) s += __shfl_xor_sync(FULL, s, off);
        if (lane == 0) sh_wred[g][gwid] = s;
        GBAR();
        const float tot = sh_wred[g][0] + sh_wred[g][1] + sh_wred[g][2] + sh_wred[g][3];
        const float inv = 1.f / tot;

        // -- probs out + V gather + context --
        float* orow = out + 8 + ((size_t)(b * NN + row)) * KSEL;
        const float* vbase = g_v + (size_t)b * NN * HID;
        float p0 = e0 * inv;
        orow[gtid] = p0;
        unsigned gidx0 = ~(unsigned)(v0 & 0xffffffffull);
        float cd[HID];
        {
            const float2* vp = (const float2*)(vbase + (size_t)gidx0 * HID);
            float2 a0 = vp[0], a1 = vp[1], a2 = vp[2], a3 = vp[3], a4 = vp[4];
            cd[0] = p0 * a0.x; cd[1] = p0 * a0.y;
            cd[2] = p0 * a1.x; cd[3] = p0 * a1.y;
            cd[4] = p0 * a2.x; cd[5] = p0 * a2.y;
            cd[6] = p0 * a3.x; cd[7] = p0 * a3.y;
            cd[8] = p0 * a4.x; cd[9] = p0 * a4.y;
        }
        if (act1) {
            float p1 = e1 * inv;
            orow[gtid + 128] = p1;
            unsigned gidx1 = ~(unsigned)(v1 & 0xffffffffull);
            const float2* vp = (const float2*)(vbase + (size_t)gidx1 * HID);
            float2 a0 = vp[0], a1 = vp[1], a2 = vp[2], a3 = vp[3], a4 = vp[4];
            cd[0] += p1 * a0.x; cd[1] += p1 * a0.y;
            cd[2] += p1 * a1.x; cd[3] += p1 * a1.y;
            cd[4] += p1 * a2.x; cd[5] += p1 * a2.y;
            cd[6] += p1 * a3.x; cd[7] += p1 * a3.y;
            cd[8] += p1 * a4.x; cd[9] += p1 * a4.y;
        }
#pragma unroll
        for (int d = 0; d < HID; d++)
#pragma unroll
            for (int off = 16; off > 0; off >>= 1)
                cd[d] += __shfl_xor_sync(FULL, cd[d], off);
        if (lane == 0) {
#pragma unroll
            for (int d = 0; d < HID; d++) sh_gctx[g][gwid][d] = cd[d];
        }
        GBAR();
        if (gtid < HID) {
            sh_sctx[g][gtid] = sh_gctx[g][0][gtid] + sh_gctx[g][1][gtid] +
                               sh_gctx[g][2][gtid] + sh_gctx[g][3][gtid];
        }
        GBAR();
        if (gwid == 0) {
            float sa = 0.f;
            if (lane < AFN) {
                sa = battn[lane];
#pragma unroll
                for (int d = 0; d < HID; d++) sa += sh_sctx[g][d] * wattn[lane * HID + d];
            }
            float t0 = (lane < AFN) ? sa * wmil[lane] : 0.f;
            float t1 = (lane < AFN) ? sa * wmil[AFN + lane] : 0.f;
#pragma unroll
            for (int off = 16; off > 0; off >>= 1) {
                t0 += __shfl_xor_sync(FULL, t0, off);
                t1 += __shfl_xor_sync(FULL, t1, off);
            }
            if (lane == 0) {
                g_logits[(b * NN + row) * 2 + 0] = t0 + bmil[0];
                g_logits[(b * NN + row) * 2 + 1] = t1 + bmil[1];
            }
        }
    }
}

// ---------------- Kernel 3: deterministic pooled reduction (8 blocks) ----------------
__global__ __launch_bounds__(256) void pool_kernel(float* __restrict__ out) {
    __shared__ float wr[8];
    const int b = blockIdx.x >> 1, c = blockIdx.x & 1;
    const int tid = threadIdx.x, lane = tid & 31, w = tid >> 5;
    float acc = 0.f;
#pragma unroll
    for (int it = 0; it < NN / 256; it++)
        acc += g_logits[((size_t)b * NN + it * 256 + tid) * 2 + c];
#pragma unroll
    for (int off = 16; off > 0; off >>= 1) acc += __shfl_xor_sync(FULL, acc, off);
    if (lane == 0) wr[w] = acc;
    __syncthreads();
    if (tid == 0) {
        float t = 0.f;
#pragma unroll
        for (int i = 0; i < 8; i++) t += wr[i];
        out[b * 2 + c] = t * (1.0f / (float)NN);
    }
}

// ---------------- launcher ----------------
extern "C" void kernel_launch(void* const* d_in, const int* in_sizes, int n_in,
                              void* d_out, int out_size) {
    const float* x   = (const float*)d_in[0];
    const float* cw2 = (const float*)d_in[1];  const float* cb2 = (const float*)d_in[2];
    const float* cw3 = (const float*)d_in[3];  const float* cb3 = (const float*)d_in[4];
    const float* cw4 = (const float*)d_in[5];  const float* cb4 = (const float*)d_in[6];
    const float* cw5 = (const float*)d_in[7];  const float* cb5 = (const float*)d_in[8];
    const float* cw6 = (const float*)d_in[9];  const float* cb6 = (const float*)d_in[10];
    const float* cw7 = (const float*)d_in[11]; const float* cb7 = (const float*)d_in[12];
    const float* wq  = (const float*)d_in[13]; const float* bq  = (const float*)d_in[14];
    const float* wk  = (const float*)d_in[15]; const float* bk  = (const float*)d_in[16];
    const float* wv  = (const float*)d_in[17]; const float* bv  = (const float*)d_in[18];
    const float* wat = (const float*)d_in[19]; const float* bat = (const float*)d_in[20];
    const float* wm  = (const float*)d_in[21]; const float* bm  = (const float*)d_in[22];
    float* out = (float*)d_out;

    cudaFuncSetAttribute(attn_kernel, cudaFuncAttributeMaxDynamicSharedMemorySize, SMEM_BYTES);

    conv_qkv_kernel<<<(BB * NN) / 8, 256>>>(x, cw2, cb2, cw3, cb3, cw4, cb4,
                                            cw5, cb5, cw6, cb6, cw7, cb7,
                                            wq, bq, wk, bk, wv, bv);
    attn_kernel<<<dim3(NN / RPB, BB), 256, SMEM_BYTES>>>(wat, bat, wm, bm, out);
    pool_kernel<<<8, 256>>>(out);
}

// round 17
// speedup vs baseline: 1.2761x; 1.0309x over previous
#include <cuda_runtime.h>
#include <math_constants.h>

// Problem constants
#define BB 4
#define NN 4096
#define FF 15
#define AA 24
#define AFN 14
#define HID 10
#define KSEL 204
#define SCALE 0.31622776601683794f   // 1/sqrt(10)
#define RPB 2                        // rows per attn block (1 per group)
#define FULL 0xffffffffu

typedef unsigned long long ull;

// ---------------- scratch (device globals; no allocation allowed) ----------------
__device__ float g_q[BB * NN * HID];          // [b][n][d]
__device__ float g_kT[BB * HID * NN];         // [b][d][n]  (transposed, fp32)
__device__ float g_v[BB * NN * HID];          // [b][n][d]
__device__ float g_logits[BB * NN * 2];       // [b][n][c]

// ---------------- helpers ----------------
__device__ __forceinline__ unsigned orderf(float f) {
    unsigned u = __float_as_uint(f);
    return (u & 0x80000000u) ? ~u : (u | 0x80000000u);
}
__device__ __forceinline__ float unorderf(unsigned u) {
    return (u & 0x80000000u) ? __uint_as_float(u ^ 0x80000000u)
                             : __uint_as_float(~u);
}

// ---------------- Kernel 1: conv features (warp per seq) + QKV projection ----------------
__global__ __launch_bounds__(256) void conv_qkv_kernel(
    const float* __restrict__ x,
    const float* __restrict__ cw2, const float* __restrict__ cb2,
    const float* __restrict__ cw3, const float* __restrict__ cb3,
    const float* __restrict__ cw4, const float* __restrict__ cb4,
    const float* __restrict__ cw5, const float* __restrict__ cb5,
    const float* __restrict__ cw6, const float* __restrict__ cb6,
    const float* __restrict__ cw7, const float* __restrict__ cb7,
    const float* __restrict__ wq, const float* __restrict__ bq,
    const float* __restrict__ wk, const float* __restrict__ bk,
    const float* __restrict__ wv, const float* __restrict__ bv) {
    __shared__ __align__(16) float wsm[FF * 56];   // [i][packed 56]
    __shared__ float bsm[AFN];
    __shared__ float xsm[8][FF * 32];              // per-seq x rows padded to 32

    const int tid = threadIdx.x;
    const int lane = tid & 31;
    const int w = tid >> 5;
    const int seq = blockIdx.x * 8 + w;

    for (int e = tid; e < FF * 56; e += 256) {
        int i = e / 56, r = e % 56;
        int f, dt;
        if (r < 6)       { f = r >> 1;            dt = r & 1; }
        else if (r < 15) { f = 3 + (r - 6) / 3;   dt = (r - 6) % 3; }
        else if (r < 27) { f = 6 + (r - 15) / 4;  dt = (r - 15) & 3; }
        else if (r < 37) { f = 9 + (r - 27) / 5;  dt = (r - 27) % 5; }
        else if (r < 49) { f = 11 + (r - 37) / 6; dt = (r - 37) % 6; }
        else             { f = 13;                dt = r - 49; }
        const float* src; int H, fl;
        if (f < 3)       { src = cw2; H = 2; fl = f; }
        else if (f < 6)  { src = cw3; H = 3; fl = f - 3; }
        else if (f < 9)  { src = cw4; H = 4; fl = f - 6; }
        else if (f < 11) { src = cw5; H = 5; fl = f - 9; }
        else if (f < 13) { src = cw6; H = 6; fl = f - 11; }
        else             { src = cw7; H = 7; fl = 0; }
        wsm[i * 56 + r] = src[(fl * FF + i) * H + dt];
    }
    if (tid < AFN) {
        float bv_;
        if (tid < 3)       bv_ = cb2[tid];
        else if (tid < 6)  bv_ = cb3[tid - 3];
        else if (tid < 9)  bv_ = cb4[tid - 6];
        else if (tid < 11) bv_ = cb5[tid - 9];
        else if (tid < 13) bv_ = cb6[tid - 11];
        else               bv_ = cb7[0];
        bsm[tid] = bv_;
    }

    const float* xg = x + (size_t)seq * (FF * AA);
    for (int idx = lane; idx < FF * AA; idx += 32) {
        int i = idx / AA, c = idx % AA;
        xsm[w][i * 32 + c] = xg[idx];
    }
    for (int p = lane; p < FF * 8; p += 32) {
        int i = p / 8, c = 24 + (p & 7);
        xsm[w][i * 32 + c] = 0.f;
    }
    __syncthreads();

    const int Hs[14] = {2,2,2,3,3,3,4,4,4,5,5,6,6,7};
    const int FO[14] = {0,2,4,6,9,12,15,19,23,27,32,37,43,49};
    float y[AFN];
#pragma unroll
    for (int f = 0; f < AFN; f++) y[f] = 0.f;
    const int t = lane;
    if (t < AA) {
#pragma unroll
        for (int i = 0; i < FF; i++) {
            float xw[7];
#pragma unroll
            for (int dt = 0; dt < 7; dt++) xw[dt] = xsm[w][i * 32 + t + dt];
            float W[56];
            const float4* wp = (const float4*)(wsm + i * 56);
#pragma unroll
            for (int q4 = 0; q4 < 14; q4++) ((float4*)W)[q4] = wp[q4];
#pragma unroll
            for (int f = 0; f < AFN; f++)
#pragma unroll
                for (int dt = 0; dt < Hs[f]; dt++)
                    y[f] += xw[dt] * W[FO[f] + dt];
        }
    }
    float feat[AFN];
#pragma unroll
    for (int f = 0; f < AFN; f++) {
        const int T = AA - Hs[f] + 1;
        float v = (t < T) ? y[f] : -CUDART_INF_F;
#pragma unroll
        for (int off = 16; off > 0; off >>= 1)
            v = fmaxf(v, __shfl_xor_sync(FULL, v, off));
        feat[f] = fmaxf(v + bsm[f], 0.f);
    }

    if (lane < 30) {
        int which = lane / 10, oo = lane % 10;
        const float* W; const float* Bv;
        if (which == 0)      { W = wq; Bv = bq; }
        else if (which == 1) { W = wk; Bv = bk; }
        else                 { W = wv; Bv = bv; }
        float acc = Bv[oo];
#pragma unroll
        for (int i = 0; i < AFN; i++) acc += feat[i] * W[oo * AFN + i];
        int b = seq >> 12, n = seq & 4095;
        if (which == 0)      g_q[(b * NN + n) * HID + oo] = acc;
        else if (which == 1) g_kT[(b * HID + oo) * NN + n] = acc;
        else                 g_v[(b * NN + n) * HID + oo] = acc;
    }
}

// ---------------- Kernel 2: attention — vectorized column mapping j = tid*4 + chunk*1024 ----------------
// dynamic smem (bytes): keys RPB*NN*4 = 32768 | hist 4*256*4 = 4096 | cand 2*256*8 = 4096
#define KEYS_U32 (RPB * NN)
#define SMEM_BYTES (KEYS_U32 * 4 + 4 * 256 * 4 + 2 * 256 * 8)

#define GBAR() asm volatile("bar.sync %0, %1;" :: "r"(g + 1), "r"(128) : "memory")

__global__ __launch_bounds__(256, 5) void attn_kernel(
    const float* __restrict__ wattn, const float* __restrict__ battn,
    const float* __restrict__ wmil, const float* __restrict__ bmil,
    float* __restrict__ out) {
    extern __shared__ unsigned smem_u[];
    unsigned* keys = smem_u;                      // indexed by column j
    unsigned* hist = smem_u + KEYS_U32;
    ull*      cand = (ull*)(smem_u + KEYS_U32 + 4 * 256);

    __shared__ float    sh_q2[RPB * HID];
    __shared__ unsigned sh_pref[2];
    __shared__ int      sh_kneed[2];
    __shared__ unsigned sh_wcnt[2][4];
    __shared__ float    sh_wred[2][4];
    __shared__ float    sh_gctx[2][4][HID];
    __shared__ float    sh_sctx[2][HID];
    __shared__ float    sh_smax[2];

    const int b = blockIdx.y;
    const int r0 = blockIdx.x * RPB;
    const int tid = threadIdx.x;
    const int lane = tid & 31;
    const int wid = tid >> 5;
    const int g = wid >> 2;          // group 0: warps 0-3, group 1: warps 4-7
    const int gtid = tid & 127;
    const int gwid = wid & 3;
    const int hc = wid & 1;          // histogram copy
    unsigned* hw = hist + (g * 2 + hc) * 256;   // 2 hist copies per group
    ull* gc = cand + g * 256;

    if (tid < RPB * HID) sh_q2[tid] = g_q[((size_t)b * NN + r0) * HID + tid];
    __syncthreads();

    // ---- Phase A: scores for 2 rows -> ordered keys in smem (vectorized) ----
    // thread tid owns columns j = tid*4 + chunk*1024 + {0..3}, chunk = 2h + c
    const float* kt = g_kT + (size_t)b * HID * NN;
#pragma unroll
    for (int h = 0; h < 2; h++) {
        float acc[RPB][8];
#pragma unroll
        for (int r = 0; r < RPB; r++)
#pragma unroll
            for (int i = 0; i < 8; i++) acc[r][i] = 0.f;
#pragma unroll
        for (int d = 0; d < HID; d++) {
            float4 kv0 = *(const float4*)(kt + d * NN + tid * 4 + (2 * h) * 1024);
            float4 kv1 = *(const float4*)(kt + d * NN + tid * 4 + (2 * h + 1) * 1024);
#pragma unroll
            for (int r = 0; r < RPB; r++) {
                float qv = sh_q2[r * HID + d];
                acc[r][0] = fmaf(qv, kv0.x, acc[r][0]);
                acc[r][1] = fmaf(qv, kv0.y, acc[r][1]);
                acc[r][2] = fmaf(qv, kv0.z, acc[r][2]);
                acc[r][3] = fmaf(qv, kv0.w, acc[r][3]);
                acc[r][4] = fmaf(qv, kv1.x, acc[r][4]);
                acc[r][5] = fmaf(qv, kv1.y, acc[r][5]);
                acc[r][6] = fmaf(qv, kv1.z, acc[r][6]);
                acc[r][7] = fmaf(qv, kv1.w, acc[r][7]);
            }
        }
#pragma unroll
        for (int r = 0; r < RPB; r++) {
            uint4 o0, o1;
            o0.x = orderf(acc[r][0]); o0.y = orderf(acc[r][1]);
            o0.z = orderf(acc[r][2]); o0.w = orderf(acc[r][3]);
            o1.x = orderf(acc[r][4]); o1.y = orderf(acc[r][5]);
            o1.z = orderf(acc[r][6]); o1.w = orderf(acc[r][7]);
            *(uint4*)(keys + r * NN + tid * 4 + (2 * h) * 1024)     = o0;
            *(uint4*)(keys + r * NN + tid * 4 + (2 * h + 1) * 1024) = o1;
        }
    }
    __syncthreads();

    // ---- group g owns row r0+g; fully independent (named barriers only) ----
    {
        const int row = r0 + g;
        const unsigned* krow = keys + g * NN;
        const uint4* krow4 = (const uint4*)krow;   // element e covers columns 4e..4e+3

        // -- pass 0: top byte histogram (vectorized scan) --
        hist[(g * 2) * 256 + gtid] = 0u; hist[(g * 2) * 256 + gtid + 128] = 0u;
        hist[(g * 2 + 1) * 256 + gtid] = 0u; hist[(g * 2 + 1) * 256 + gtid + 128] = 0u;
        if (gtid == 0) { sh_pref[g] = 0u; sh_kneed[g] = KSEL; }
        GBAR();
#pragma unroll
        for (int c = 0; c < 8; c++) {
            uint4 kk = krow4[gtid + (c << 7)];
            atomicAdd(&hw[kk.x >> 24], 1u);
            atomicAdd(&hw[kk.y >> 24], 1u);
            atomicAdd(&hw[kk.z >> 24], 1u);
            atomicAdd(&hw[kk.w >> 24], 1u);
        }
        GBAR();
        if (gwid == 0) {
            unsigned pref = sh_pref[g];
            int kneed = sh_kneed[g];
            unsigned h8[8];
            int part = 0;
#pragma unroll
            for (int i = 0; i < 8; i++) {
                unsigned s = hist[(g * 2) * 256 + lane * 8 + i] +
                             hist[(g * 2 + 1) * 256 + lane * 8 + i];
                h8[i] = s; part += (int)s;
            }
            int suff = part;
#pragma unroll
            for (int d2 = 1; d2 < 32; d2 <<= 1) {
                int v = __shfl_down_sync(FULL, suff, d2);
                if (lane + d2 < 32) suff += v;
            }
            int c = suff - part;
            bool found = false; unsigned bsel = 0; int krem = 0;
#pragma unroll
            for (int i = 7; i >= 0; i--) {
                int Cn = c; c += (int)h8[i];
                if (!found && c >= kneed && Cn < kneed) {
                    bsel = (unsigned)(lane * 8 + i); krem = kneed - Cn; found = true;
                }
            }
            unsigned fm = __ballot_sync(FULL, found);
            int src = __ffs(fm) - 1;
            if (lane == src) { sh_pref[g] = (pref << 8) | bsel; sh_kneed[g] = krem; }
        }
        GBAR();
        const unsigned pref8 = sh_pref[g];

        // -- clear + pass 1: byte 1 within selected bucket --
        hist[(g * 2) * 256 + gtid] = 0u; hist[(g * 2) * 256 + gtid + 128] = 0u;
        hist[(g * 2 + 1) * 256 + gtid] = 0u; hist[(g * 2 + 1) * 256 + gtid + 128] = 0u;
        GBAR();
#pragma unroll
        for (int c = 0; c < 8; c++) {
            uint4 kk = krow4[gtid + (c << 7)];
            if ((kk.x >> 24) == pref8) atomicAdd(&hw[(kk.x >> 16) & 255u], 1u);
            if ((kk.y >> 24) == pref8) atomicAdd(&hw[(kk.y >> 16) & 255u], 1u);
            if ((kk.z >> 24) == pref8) atomicAdd(&hw[(kk.z >> 16) & 255u], 1u);
            if ((kk.w >> 24) == pref8) atomicAdd(&hw[(kk.w >> 16) & 255u], 1u);
        }
        GBAR();
        if (gwid == 0) {
            unsigned pref = sh_pref[g];
            int kneed = sh_kneed[g];
            unsigned h8[8];
            int part = 0;
#pragma unroll
            for (int i = 0; i < 8; i++) {
                unsigned s = hist[(g * 2) * 256 + lane * 8 + i] +
                             hist[(g * 2 + 1) * 256 + lane * 8 + i];
                h8[i] = s; part += (int)s;
            }
            int suff = part;
#pragma unroll
            for (int d2 = 1; d2 < 32; d2 <<= 1) {
                int v = __shfl_down_sync(FULL, suff, d2);
                if (lane + d2 < 32) suff += v;
            }
            int c = suff - part;
            bool found = false; unsigned bsel = 0; int krem = 0;
#pragma unroll
            for (int i = 7; i >= 0; i--) {
                int Cn = c; c += (int)h8[i];
                if (!found && c >= kneed && Cn < kneed) {
                    bsel = (unsigned)(lane * 8 + i); krem = kneed - Cn; found = true;
                }
            }
            unsigned fm = __ballot_sync(FULL, found);
            int src = __ffs(fm) - 1;
            if (lane == src) { sh_pref[g] = (pref << 8) | bsel; sh_kneed[g] = krem; }
        }
        GBAR();
        const unsigned pref16 = sh_pref[g];

        // -- compact candidates (u>>16 >= pref16) into gc[256], two-phase, vectorized --
        unsigned totc;
        {
            unsigned wcnt = 0;
#pragma unroll
            for (int c = 0; c < 8; c++) {
                uint4 kk = krow4[gtid + (c << 7)];
                wcnt += (unsigned)__popc(__ballot_sync(FULL, (kk.x >> 16) >= pref16));
                wcnt += (unsigned)__popc(__ballot_sync(FULL, (kk.y >> 16) >= pref16));
                wcnt += (unsigned)__popc(__ballot_sync(FULL, (kk.z >> 16) >= pref16));
                wcnt += (unsigned)__popc(__ballot_sync(FULL, (kk.w >> 16) >= pref16));
            }
            if (lane == 0) sh_wcnt[g][gwid] = wcnt;
            gc[gtid] = 0ull; gc[gtid + 128] = 0ull;
            GBAR();
            unsigned base = 0; totc = 0;
#pragma unroll
            for (int w2 = 0; w2 < 4; w2++) {
                unsigned c = sh_wcnt[g][w2];
                if (w2 < gwid) base += c;
                totc += c;
            }
#pragma unroll
            for (int c = 0; c < 8; c++) {
                uint4 kk = krow4[gtid + (c << 7)];
                unsigned jb = (unsigned)((gtid + (c << 7)) << 2);
                unsigned uu[4] = {kk.x, kk.y, kk.z, kk.w};
#pragma unroll
                for (int sub = 0; sub < 4; sub++) {
                    unsigned u = uu[sub];
                    bool p = (u >> 16) >= pref16;
                    unsigned mm = __ballot_sync(FULL, p);
                    if (p) {
                        unsigned pos = base + (unsigned)__popc(mm & ((1u << lane) - 1u));
                        if (pos < 256u)
                            gc[pos] = ((ull)u << 32) | (ull)(~(jb + (unsigned)sub));
                    }
                    base += (unsigned)__popc(mm);
                }
            }
            GBAR();
        }

        if (totc > 256u) {
            // rare fallback: refine to exact 32-bit threshold (passes 2,3), recompact
            for (int pp = 2; pp < 4; pp++) {
                const int shift = 24 - 8 * pp;
                hist[(g * 2) * 256 + gtid] = 0u; hist[(g * 2) * 256 + gtid + 128] = 0u;
                hist[(g * 2 + 1) * 256 + gtid] = 0u; hist[(g * 2 + 1) * 256 + gtid + 128] = 0u;
                GBAR();
                const unsigned prefc = sh_pref[g];
#pragma unroll
                for (int i = 0; i < 32; i++) {
                    unsigned u = krow[gtid + (i << 7)];
                    if ((u >> (shift + 8)) == prefc)
                        atomicAdd(&hw[(u >> shift) & 255u], 1u);
                }
                GBAR();
                if (gwid == 0) {
                    unsigned pref = sh_pref[g];
                    int kneed = sh_kneed[g];
                    unsigned h8[8];
                    int part = 0;
#pragma unroll
                    for (int i = 0; i < 8; i++) {
                        unsigned s = hist[(g * 2) * 256 + lane * 8 + i] +
                                     hist[(g * 2 + 1) * 256 + lane * 8 + i];
                        h8[i] = s; part += (int)s;
                    }
                    int suff = part;
#pragma unroll
                    for (int d2 = 1; d2 < 32; d2 <<= 1) {
                        int v = __shfl_down_sync(FULL, suff, d2);
                        if (lane + d2 < 32) suff += v;
                    }
                    int c = suff - part;
                    bool found = false; unsigned bsel = 0; int krem = 0;
#pragma unroll
                    for (int i = 7; i >= 0; i--) {
                        int Cn = c; c += (int)h8[i];
                        if (!found && c >= kneed && Cn < kneed) {
                            bsel = (unsigned)(lane * 8 + i); krem = kneed - Cn; found = true;
                        }
                    }
                    unsigned fm = __ballot_sync(FULL, found);
                    int src = __ffs(fm) - 1;
                    if (lane == src) { sh_pref[g] = (pref << 8) | bsel; sh_kneed[g] = krem; }
                }
                GBAR();
            }
            const unsigned T = sh_pref[g];
            unsigned wcnt = 0;
#pragma unroll
            for (int i = 0; i < 32; i++) {
                bool p = krow[gtid + (i << 7)] >= T;
                wcnt += (unsigned)__popc(__ballot_sync(FULL, p));
            }
            if (lane == 0) sh_wcnt[g][gwid] = wcnt;
            gc[gtid] = 0ull; gc[gtid + 128] = 0ull;
            GBAR();
            unsigned base = 0;
#pragma unroll
            for (int w2 = 0; w2 < 4; w2++)
                if (w2 < gwid) base += sh_wcnt[g][w2];
#pragma unroll
            for (int i = 0; i < 32; i++) {
                unsigned x2 = gtid + (i << 7);
                unsigned u = krow[x2];
                bool p = (u >= T);
                unsigned mm = __ballot_sync(FULL, p);
                if (p) {
                    unsigned pos = base + (unsigned)__popc(mm & ((1u << lane) - 1u));
                    if (pos < 256u) gc[pos] = ((ull)u << 32) | (ull)(~x2);
                }
                base += (unsigned)__popc(mm);
            }
            GBAR();
        }

        // -- bitonic sort 256 elems, 128 threads x 2 (elem i: owner i&127, half i>>7) --
        // descending; composite key (value desc, index asc) == exact lax.top_k order
        ull v0 = gc[gtid], v1 = gc[gtid + 128];
        for (int k2 = 2; k2 <= 256; k2 <<= 1) {
            for (int j = k2 >> 1; j > 0; j >>= 1) {
                if (j == 128) {
                    ull mx = (v0 > v1) ? v0 : v1;
                    ull mn = (v0 > v1) ? v1 : v0;
                    v0 = mx; v1 = mn;
                } else if (j >= 32) {
                    gc[gtid] = v0; gc[gtid + 128] = v1;
                    GBAR();
                    ull o0 = gc[gtid ^ j], o1 = gc[(gtid ^ j) + 128];
                    GBAR();
                    {
                        bool up = ((gtid & k2) == 0);
                        bool lower = ((gtid & j) == 0);
                        bool tkm = (up == lower);
                        ull mx = (v0 > o0) ? v0 : o0, mn = (v0 > o0) ? o0 : v0;
                        v0 = tkm ? mx : mn;
                    }
                    {
                        int i1 = gtid + 128;
                        bool up = ((i1 & k2) == 0);
                        bool lower = ((i1 & j) == 0);
                        bool tkm = (up == lower);
                        ull mx = (v1 > o1) ? v1 : o1, mn = (v1 > o1) ? o1 : v1;
                        v1 = tkm ? mx : mn;
                    }
                } else {
                    ull o0 = __shfl_xor_sync(FULL, v0, j);
                    ull o1 = __shfl_xor_sync(FULL, v1, j);
                    {
                        bool up = ((gtid & k2) == 0);
                        bool lower = ((gtid & j) == 0);
                        bool tkm = (up == lower);
                        ull mx = (v0 > o0) ? v0 : o0, mn = (v0 > o0) ? o0 : v0;
                        v0 = tkm ? mx : mn;
                    }
                    {
                        int i1 = gtid + 128;
                        bool up = ((i1 & k2) == 0);
                        bool lower = ((i1 & j) == 0);
                        bool tkm = (up == lower);
                        ull mx = (v1 > o1) ? v1 : o1, mn = (v1 > o1) ? o1 : v1;
                        v1 = tkm ? mx : mn;
                    }
                }
            }
        }
        // thread gtid holds ranks gtid (v0) and gtid+128 (v1)

        if (gtid == 0) sh_smax[g] = unorderf((unsigned)(v0 >> 32)) * SCALE;
        GBAR();
        const float smax = sh_smax[g];

        // -- softmax: rank gtid always < KSEL; rank gtid+128 < KSEL iff gtid < KSEL-128 --
        const bool act1 = gtid < (KSEL - 128);
        float e0 = __expf(unorderf((unsigned)(v0 >> 32)) * SCALE - smax);
        float e1 = act1 ? __expf(unorderf((unsigned)(v1 >> 32)) * SCALE - smax) : 0.f;
        float s = e0 + e1;
#pragma unroll
        for (int off = 16; off > 0; off >>= 1) s += __shfl_xor_sync(FULL, s, off);
        if (lane == 0) sh_wred[g][gwid] = s;
        GBAR();
        const float tot = sh_wred[g][0] + sh_wred[g][1] + sh_wred[g][2] + sh_wred[g][3];
        const float inv = 1.f / tot;

        // -- probs out + V gather + context --
        float* orow = out + 8 + ((size_t)(b * NN + row)) * KSEL;
        const float* vbase = g_v + (size_t)b * NN * HID;
        float p0 = e0 * inv;
        orow[gtid] = p0;
        unsigned gidx0 = ~(unsigned)(v0 & 0xffffffffull);
        float cd[HID];
        {
            const float2* vp = (const float2*)(vbase + (size_t)gidx0 * HID);
            float2 a0 = vp[0], a1 = vp[1], a2 = vp[2], a3 = vp[3], a4 = vp[4];
            cd[0] = p0 * a0.x; cd[1] = p0 * a0.y;
            cd[2] = p0 * a1.x; cd[3] = p0 * a1.y;
            cd[4] = p0 * a2.x; cd[5] = p0 * a2.y;
            cd[6] = p0 * a3.x; cd[7] = p0 * a3.y;
            cd[8] = p0 * a4.x; cd[9] = p0 * a4.y;
        }
        if (act1) {
            float p1 = e1 * inv;
            orow[gtid + 128] = p1;
            unsigned gidx1 = ~(unsigned)(v1 & 0xffffffffull);
            const float2* vp = (const float2*)(vbase + (size_t)gidx1 * HID);
            float2 a0 = vp[0], a1 = vp[1], a2 = vp[2], a3 = vp[3], a4 = vp[4];
            cd[0] += p1 * a0.x; cd[1] += p1 * a0.y;
            cd[2] += p1 * a1.x; cd[3] += p1 * a1.y;
            cd[4] += p1 * a2.x; cd[5] += p1 * a2.y;
            cd[6] += p1 * a3.x; cd[7] += p1 * a3.y;
            cd[8] += p1 * a4.x; cd[9] += p1 * a4.y;
        }
#pragma unroll
        for (int d = 0; d < HID; d++)
#pragma unroll
            for (int off = 16; off > 0; off >>= 1)
                cd[d] += __shfl_xor_sync(FULL, cd[d], off);
        if (lane == 0) {
#pragma unroll
            for (int d = 0; d < HID; d++) sh_gctx[g][gwid][d] = cd[d];
        }
        GBAR();
        if (gtid < HID) {
            sh_sctx[g][gtid] = sh_gctx[g][0][gtid] + sh_gctx[g][1][gtid] +
                               sh_gctx[g][2][gtid] + sh_gctx[g][3][gtid];
        }
        GBAR();
        if (gwid == 0) {
            float sa = 0.f;
            if (lane < AFN) {
                sa = battn[lane];
#pragma unroll
                for (int d = 0; d < HID; d++) sa += sh_sctx[g][d] * wattn[lane * HID + d];
            }
            float t0 = (lane < AFN) ? sa * wmil[lane] : 0.f;
            float t1 = (lane < AFN) ? sa * wmil[AFN + lane] : 0.f;
#pragma unroll
            for (int off = 16; off > 0; off >>= 1) {
                t0 += __shfl_xor_sync(FULL, t0, off);
                t1 += __shfl_xor_sync(FULL, t1, off);
            }
            if (lane == 0) {
                g_logits[(b * NN + row) * 2 + 0] = t0 + bmil[0];
                g_logits[(b * NN + row) * 2 + 1] = t1 + bmil[1];
            }
        }
    }
}

// ---------------- Kernel 3: deterministic pooled reduction (8 blocks) ----------------
__global__ __launch_bounds__(256) void pool_kernel(float* __restrict__ out) {
    __shared__ float wr[8];
    const int b = blockIdx.x >> 1, c = blockIdx.x & 1;
    const int tid = threadIdx.x, lane = tid & 31, w = tid >> 5;
    float acc = 0.f;
#pragma unroll
    for (int it = 0; it < NN / 256; it++)
        acc += g_logits[((size_t)b * NN + it * 256 + tid) * 2 + c];
#pragma unroll
    for (int off = 16; off > 0; off >>= 1) acc += __shfl_xor_sync(FULL, acc, off);
    if (lane == 0) wr[w] = acc;
    __syncthreads();
    if (tid == 0) {
        float t = 0.f;
#pragma unroll
        for (int i = 0; i < 8; i++) t += wr[i];
        out[b * 2 + c] = t * (1.0f / (float)NN);
    }
}

// ---------------- launcher ----------------
extern "C" void kernel_launch(void* const* d_in, const int* in_sizes, int n_in,
                              void* d_out, int out_size) {
    const float* x   = (const float*)d_in[0];
    const float* cw2 = (const float*)d_in[1];  const float* cb2 = (const float*)d_in[2];
    const float* cw3 = (const float*)d_in[3];  const float* cb3 = (const float*)d_in[4];
    const float* cw4 = (const float*)d_in[5];  const float* cb4 = (const float*)d_in[6];
    const float* cw5 = (const float*)d_in[7];  const float* cb5 = (const float*)d_in[8];
    const float* cw6 = (const float*)d_in[9];  const float* cb6 = (const float*)d_in[10];
    const float* cw7 = (const float*)d_in[11]; const float* cb7 = (const float*)d_in[12];
    const float* wq  = (const float*)d_in[13]; const float* bq  = (const float*)d_in[14];
    const float* wk  = (const float*)d_in[15]; const float* bk  = (const float*)d_in[16];
    const float* wv  = (const float*)d_in[17]; const float* bv  = (const float*)d_in[18];
    const float* wat = (const float*)d_in[19]; const float* bat = (const float*)d_in[20];
    const float* wm  = (const float*)d_in[21]; const float* bm  = (const float*)d_in[22];
    float* out = (float*)d_out;

    cudaFuncSetAttribute(attn_kernel, cudaFuncAttributeMaxDynamicSharedMemorySize, SMEM_BYTES);

    conv_qkv_kernel<<<(BB * NN) / 8, 256>>>(x, cw2, cb2, cw3, cb3, cw4, cb4,
                                            cw5, cb5, cw6, cb6, cw7, cb7,
                                            wq, bq, wk, bk, wv, bv);
    attn_kernel<<<dim3(NN / RPB, BB), 256, SMEM_BYTES>>>(wat, bat, wm, bm, out);
    pool_kernel<<<8, 256>>>(out);
}